// round 12
// baseline (speedup 1.0000x reference)
#include <cuda_runtime.h>
#include <cuda_bf16.h>
#include <cuda_fp16.h>
#include <math.h>
#include <cstdint>

// Fixed problem shapes
#define B_   4
#define T_   2048
#define C_   768
#define H_   12
#define D_   64
#define M_   (B_ * T_)    // 8192
#define N1_  (3 * C_)     // 2304
#define BHD  (B_ * H_)    // 48

// ---------------- scratch (device globals; referenced ONLY in device code) --------
__device__ float g_cosT[T_ * (D_ / 2)];
__device__ float g_sinT[T_ * (D_ / 2)];

// fp16 operand buffers (single-pass everywhere; fp32 accumulate)
__device__ __half g_xf[M_ * C_];         // x
__device__ __half g_yf[M_ * C_];         // attn out
__device__ __half g_waf[N1_ * C_];       // W_attn^T [N][K]
__device__ __half g_wpf[C_ * C_];        // W_proj^T [N][K]
__device__ __half g_qh[BHD * T_ * D_];   // roped q (scaled 1/8), [B,H,T,D]
__device__ __half g_kh[BHD * T_ * D_];   // roped k
__device__ __half g_vth[BHD * D_ * T_];  // V^T [B,H,D,T]

// ---------------- helpers -----------------------------------------------------------
__device__ __forceinline__ uint32_t smem_u32(const void* p) {
    uint32_t a;
    asm("{ .reg .u64 t; cvta.to.shared.u64 t, %1; cvt.u32.u64 %0, t; }" : "=r"(a) : "l"(p));
    return a;
}
#define LDSM_X4(r, a)                                                           \
    asm volatile("ldmatrix.sync.aligned.m8n8.x4.shared.b16 {%0,%1,%2,%3},[%4];" \
        : "=r"((r)[0]), "=r"((r)[1]), "=r"((r)[2]), "=r"((r)[3]) : "r"(a))
#define MMAF16(d, a, b0, b1)                                                    \
    asm volatile("mma.sync.aligned.m16n8k16.row.col.f32.f16.f16.f32 "           \
        "{%0,%1,%2,%3},{%4,%5,%6,%7},{%8,%9},{%0,%1,%2,%3};"                    \
        : "+f"((d)[0]), "+f"((d)[1]), "+f"((d)[2]), "+f"((d)[3])                \
        : "r"((a)[0]), "r"((a)[1]), "r"((a)[2]), "r"((a)[3]), "r"(b0), "r"(b1))
#define CP16(dst, src) \
    asm volatile("cp.async.cg.shared.global [%0], [%1], 16;" :: "r"(dst), "l"(src))

__device__ __forceinline__ uint32_t h2(float a, float b) {
    __half2 t = __floats2half2_rn(a, b);
    return *(uint32_t*)&t;
}

// ---------------- merged prep: tables + x convert + both W transposes --------------
// Flat grid of 256-thread blocks:
//   [0, 1536)            : x fp32 -> fp16 (float4 per thread)
//   [1536, 3264)         : W_attn^T  (72 x 24 tiles of 32x32)
//   [3264, 3840)         : W_proj^T  (24 x 24 tiles)
//   [3840, 4096)         : RoPE tables
#define PREP_XB   (M_ * C_ / 4 / 256)        // 1536
#define PREP_WAB  ((N1_ / 32) * (C_ / 32))   // 1728
#define PREP_WPB  ((C_ / 32) * (C_ / 32))    // 576
#define PREP_TB   (T_ * 32 / 256)            // 256
#define PREP_BLOCKS (PREP_XB + PREP_WAB + PREP_WPB + PREP_TB)

__global__ void prep_kernel(const float* __restrict__ x,
                            const float* __restrict__ Wa,
                            const float* __restrict__ Wp) {
    __shared__ float tile[32][33];
    const int blk = blockIdx.x;
    const int tid = threadIdx.x;

    if (blk < PREP_XB) {
        int i = blk * 256 + tid;
        float4 v = ((const float4*)x)[i];
        ((uint2*)g_xf)[i] = make_uint2(h2(v.x, v.y), h2(v.z, v.w));
        return;
    }

    const float* W;
    __half* Th;
    int N, bi;
    if (blk < PREP_XB + PREP_WAB) {
        bi = blk - PREP_XB;  W = Wa;  Th = g_waf;  N = N1_;
    } else if (blk < PREP_XB + PREP_WAB + PREP_WPB) {
        bi = blk - PREP_XB - PREP_WAB;  W = Wp;  Th = g_wpf;  N = C_;
    } else {
        int idx = (blk - PREP_XB - PREP_WAB - PREP_WPB) * 256 + tid;
        int t = idx >> 5;
        int i = idx & 31;
        double inv = exp(-((double)i / 32.0) * log(10000.0));
        double ang = (double)t * inv;
        g_cosT[idx] = (float)cos(ang);
        g_sinT[idx] = (float)sin(ang);
        return;
    }
    // 32x32 transpose tile: bi = kb * (N/32) + nb
    const int nbt = N / 32;
    const int kb = bi / nbt, nb = bi - kb * nbt;
    const int k0 = kb * 32, n0 = nb * 32;
    const int tx = tid & 31, ty = tid >> 5;    // 32 x 8
    for (int r = ty; r < 32; r += 8)
        tile[r][tx] = W[(size_t)(k0 + r) * N + n0 + tx];
    __syncthreads();
    for (int r = ty; r < 32; r += 8)
        Th[(size_t)(n0 + r) * C_ + k0 + tx] = __float2half(tile[tx][r]);
}

// ---------------- mma.sync GEMM: fp16 single-pass, fp32 accum (unchanged) -----------
#define TILE_B    10240
#define STAGE_B   (2 * TILE_B)
#define GEMM_SMEM 67584

template <int NT, int EPI>
__global__ __launch_bounds__(256, 2) void tc_gemm_kernel(
    const float* __restrict__ bias, float* __restrict__ Cout)
{
    extern __shared__ __align__(128) char smem[];
    const uint32_t sb0 = smem_u32(smem);
    const int tid  = threadIdx.x;
    const int lane = tid & 31;
    const int warp = tid >> 5;
    const int m_w  = (warp >> 1) * 32;
    const int n_w  = (warp & 1) * 64;
    const int m0 = blockIdx.y * 128;
    const int n0 = blockIdx.x * 128;

    const __half* Asrc = (EPI == 1) ? g_xf  : g_yf;
    const __half* Bsrc = (EPI == 1) ? g_waf : g_wpf;

    auto load_chunk = [&](int kc, int st) {
        const uint32_t sbase = sb0 + (uint32_t)st * STAGE_B;
        const int k0 = kc * 32;
#pragma unroll
        for (int it = 0; it < 4; ++it) {
            int idx  = it * 256 + tid;
            int tile = idx >> 9;
            int r    = (idx >> 2) & 127;
            int seg  = idx & 3;
            const __half* src = tile ? Bsrc : Asrc;
            int rowbase = (tile ? n0 : m0) + r;
            const void* g = src + (size_t)rowbase * C_ + k0 + seg * 8;
            uint32_t dst = sbase + (uint32_t)tile * TILE_B + (uint32_t)(r * 80 + seg * 16);
            CP16(dst, g);
        }
        asm volatile("cp.async.commit_group;" ::: "memory");
    };

    float acc[2][8][4];
#pragma unroll
    for (int i = 0; i < 2; i++)
#pragma unroll
        for (int j = 0; j < 8; j++)
#pragma unroll
            for (int r = 0; r < 4; r++) acc[i][j][r] = 0.f;

    load_chunk(0, 0);
    const int NCHUNK = C_ / 32;
    for (int c = 0; c < NCHUNK; ++c) {
        const int st = c & 1;
        if (c + 1 < NCHUNK) {
            load_chunk(c + 1, st ^ 1);
            asm volatile("cp.async.wait_group 1;" ::: "memory");
        } else {
            asm volatile("cp.async.wait_group 0;" ::: "memory");
        }
        __syncthreads();

        const uint32_t sA = sb0 + (uint32_t)st * STAGE_B;
        const uint32_t sB = sA + TILE_B;

        uint32_t af[2][2][4];
#pragma unroll
        for (int ks = 0; ks < 2; ks++)
#pragma unroll
            for (int i = 0; i < 2; i++) {
                uint32_t ra = (uint32_t)((m_w + i * 16 + (lane & 15)) * 80 +
                                         ks * 32 + ((lane >> 4) & 1) * 16);
                LDSM_X4(af[ks][i], sA + ra);
            }
#pragma unroll
        for (int j = 0; j < 8; j++) {
            uint32_t rb = (uint32_t)((n_w + j * 8 + (lane & 7)) * 80 +
                                     ((lane >> 3) & 3) * 16);
            uint32_t bF[4];
            LDSM_X4(bF, sB + rb);
#pragma unroll
            for (int ks = 0; ks < 2; ks++)
#pragma unroll
                for (int i = 0; i < 2; i++)
                    MMAF16(acc[i][j], af[ks][i], bF[ks * 2], bF[ks * 2 + 1]);
        }
        __syncthreads();
    }

    float* stg = (float*)smem;
#pragma unroll
    for (int i = 0; i < 2; i++) {
        int row = m_w + i * 16 + (lane >> 2);
#pragma unroll
        for (int j = 0; j < 8; j++) {
            int col = n_w + j * 8 + (lane & 3) * 2;
            float b0 = bias[n0 + col], b1 = bias[n0 + col + 1];
            stg[row * 132 + col]           = acc[i][j][0] + b0;
            stg[row * 132 + col + 1]       = acc[i][j][1] + b1;
            stg[(row + 8) * 132 + col]     = acc[i][j][2] + b0;
            stg[(row + 8) * 132 + col + 1] = acc[i][j][3] + b1;
        }
    }
    __syncthreads();

    if (EPI == 0) {
#pragma unroll
        for (int it = 0; it < 16; ++it) {
            int idx = it * 256 + tid;
            int ml = idx >> 5;
            int c4 = (idx & 31) * 4;
            float4 v = *(const float4*)(stg + ml * 132 + c4);
            *(float4*)(Cout + (size_t)(m0 + ml) * NT + n0 + c4) = v;
        }
    } else {
        const int which = n0 / C_;
        const int hbase = (n0 % C_) / 64;
        const int bb = m0 >> 11;
        const int t0 = m0 & (T_ - 1);
        if (which < 2) {
            __half* dh = which ? g_kh : g_qh;
            const float sc = which ? 1.0f : 0.125f;
#pragma unroll
            for (int it = 0; it < 16; ++it) {
                int idx = it * 256 + tid;
                int ml = idx >> 5;
                int hl = (idx >> 4) & 1;
                int d  = (idx & 15) * 2;
                int t  = t0 + ml;
                float c0 = g_cosT[(t << 5) + d],     s0 = g_sinT[(t << 5) + d];
                float c1 = g_cosT[(t << 5) + d + 1], s1 = g_sinT[(t << 5) + d + 1];
                const float* row = stg + ml * 132 + hl * 64 + d;
                float x1a = row[0],  x1b = row[1];
                float x2a = row[32], x2b = row[33];
                float y1a = (x1a * c0 + x2a * s0) * sc;
                float y1b = (x1b * c1 + x2b * s1) * sc;
                float y2a = (-x1a * s0 + x2a * c0) * sc;
                float y2b = (-x1b * s1 + x2b * c1) * sc;
                size_t o = ((size_t)(bb * H_ + hbase + hl) * T_ + t) * 64 + d;
                *(uint32_t*)(dh + o)      = h2(y1a, y1b);
                *(uint32_t*)(dh + o + 32) = h2(y2a, y2b);
            }
        } else {
#pragma unroll
            for (int it = 0; it < 32; ++it) {
                int idx  = it * 256 + tid;
                int dcol = idx >> 6;
                int tp   = (idx & 63) * 2;
                int hl = dcol >> 6;
                int dd = dcol & 63;
                float v0 = stg[tp * 132 + dcol];
                float v1 = stg[(tp + 1) * 132 + dcol];
                size_t o = ((size_t)(bb * H_ + hbase + hl) * 64 + dd) * T_ + t0 + tp;
                *(uint32_t*)(g_vth + o) = h2(v0, v1);
            }
        }
    }
}

// ---------------- Tensor-core flash attention: fp16, 2 CTA/SM, 3-stage ring --------
// 128-k stages; softmax/PV in two 64-k halves (fits 128 regs -> 2 CTAs/SM).
// 3-stage cp.async ring: loads run 2 tiles ahead (wait_group 2).
#define KSTG  (128 * 144)                // 18432
#define VSTG  (64 * 272)                 // 17408
#define STG_BYTES (KSTG + VSTG)          // 35840
#define ATTN_SMEM (3 * STG_BYTES)        // 107520

__global__ __launch_bounds__(256, 2) void attn_mma_kernel() {
    extern __shared__ __align__(128) char sm[];
    const uint32_t sb = smem_u32(sm);
    const int tid  = threadIdx.x;
    const int lane = tid & 31;
    const int w    = tid >> 5;
    // LPT: all qb=15 tiles (across heads) first, then qb=14, ...
    const int bh   = (int)blockIdx.x % BHD;
    const int qb   = (T_ / 128) - 1 - (int)blockIdx.x / BHD;
    const int b    = bh / H_;
    const int h    = bh - b * H_;
    const size_t hb = (size_t)bh * T_ * D_;
    const int qbase = qb * 128;
    const int r0 = lane >> 2;
    const int c2 = (lane & 3) * 2;
    const int row_a = qbase + w * 16 + r0;

    // Q A-fragments: fp16, direct 4B global loads
    uint32_t qf[4][4];
#pragma unroll
    for (int ks = 0; ks < 4; ks++) {
        int d = ks * 16 + c2;
        size_t o0 = hb + (size_t)row_a * 64 + d;
        size_t o1 = hb + (size_t)(row_a + 8) * 64 + d;
        qf[ks][0] = *(const uint32_t*)(g_qh + o0);
        qf[ks][1] = *(const uint32_t*)(g_qh + o1);
        qf[ks][2] = *(const uint32_t*)(g_qh + o0 + 8);
        qf[ks][3] = *(const uint32_t*)(g_qh + o1 + 8);
    }

    const __half* kh = g_kh + hb;
    const __half* vh = g_vth + hb;

    auto load_stage = [&](int kt, int st) {
        const uint32_t sbase = sb + (uint32_t)st * STG_BYTES;
        const int kbase = kt * 128;
#pragma unroll
        for (int it = 0; it < 4; ++it) {
            int idx = it * 256 + tid;
            int r   = idx >> 3;
            int seg = idx & 7;
            const void* g = kh + (size_t)(kbase + r) * 64 + seg * 8;
            CP16(sbase + (uint32_t)(r * 144 + seg * 16), g);
        }
#pragma unroll
        for (int it = 0; it < 4; ++it) {
            int idx = it * 256 + tid;
            int r   = idx >> 4;
            int seg = idx & 15;
            const void* g = vh + (size_t)r * T_ + kbase + seg * 8;
            CP16(sbase + (uint32_t)(KSTG + r * 272 + seg * 16), g);
        }
        asm volatile("cp.async.commit_group;" ::: "memory");
    };

    float oacc[8][4];
#pragma unroll
    for (int jd = 0; jd < 8; jd++)
#pragma unroll
        for (int e = 0; e < 4; e++) oacc[jd][e] = 0.f;
    float m0 = -1e30f, m1 = -1e30f, l0 = 0.f, l1 = 0.f;

    load_stage(0, 0);
    if (1 <= qb) load_stage(1, 1);

    int st = 0;   // stage of tile kt (kt % 3)
    for (int kt = 0; kt <= qb; kt++) {
        if (kt + 2 <= qb) {
            load_stage(kt + 2, (st + 2) % 3);
            asm volatile("cp.async.wait_group 2;" ::: "memory");
        } else if (kt + 1 <= qb) {
            asm volatile("cp.async.wait_group 1;" ::: "memory");
        } else {
            asm volatile("cp.async.wait_group 0;" ::: "memory");
        }
        __syncthreads();

        const uint32_t kb = sb + (uint32_t)st * STG_BYTES;
        const uint32_t vb = kb + KSTG;

#pragma unroll
        for (int khalf = 0; khalf < 2; khalf++) {
            // Diagonal tile, upper k-half fully masked for lower 4 warps: skip.
            if (kt == qb && khalf == 1 && w < 4) continue;

            // ---- S = Q K^T over 64 k (8 n8 tiles) ----
            float sacc[8][4];
#pragma unroll
            for (int j = 0; j < 8; j++)
#pragma unroll
                for (int e = 0; e < 4; e++) sacc[j][e] = 0.f;

#pragma unroll
            for (int j = 0; j < 8; j++) {
                uint32_t rbase = kb + (uint32_t)((khalf * 64 + j * 8 + (lane & 7)) * 144 +
                                                 ((lane >> 3) & 3) * 16);
#pragma unroll
                for (int dh = 0; dh < 2; dh++) {
                    uint32_t bF[4];
                    LDSM_X4(bF, rbase + dh * 64);
#pragma unroll
                    for (int ki = 0; ki < 2; ki++)
                        MMAF16(sacc[j], qf[dh * 2 + ki], bF[ki * 2], bF[ki * 2 + 1]);
                }
            }

            // ---- causal mask on diagonal tile ----
            if (kt == qb) {
                const int kb0 = kt * 128 + khalf * 64;
#pragma unroll
                for (int j = 0; j < 8; j++) {
                    int col = kb0 + j * 8 + c2;
                    if (col > row_a)         sacc[j][0] = -1e30f;
                    if (col + 1 > row_a)     sacc[j][1] = -1e30f;
                    if (col > row_a + 8)     sacc[j][2] = -1e30f;
                    if (col + 1 > row_a + 8) sacc[j][3] = -1e30f;
                }
            }

            // ---- online softmax over this 64-k half ----
            float mx0 = -1e30f, mx1 = -1e30f;
#pragma unroll
            for (int j = 0; j < 8; j++) {
                mx0 = fmaxf(mx0, fmaxf(sacc[j][0], sacc[j][1]));
                mx1 = fmaxf(mx1, fmaxf(sacc[j][2], sacc[j][3]));
            }
            mx0 = fmaxf(mx0, __shfl_xor_sync(0xffffffffu, mx0, 1));
            mx0 = fmaxf(mx0, __shfl_xor_sync(0xffffffffu, mx0, 2));
            mx1 = fmaxf(mx1, __shfl_xor_sync(0xffffffffu, mx1, 1));
            mx1 = fmaxf(mx1, __shfl_xor_sync(0xffffffffu, mx1, 2));
            float mn0 = fmaxf(m0, mx0), mn1 = fmaxf(m1, mx1);
            float a0 = __expf(m0 - mn0), a1 = __expf(m1 - mn1);
            m0 = mn0; m1 = mn1;
            float s0 = 0.f, s1 = 0.f;
#pragma unroll
            for (int j = 0; j < 8; j++) {
                sacc[j][0] = __expf(sacc[j][0] - m0);
                sacc[j][1] = __expf(sacc[j][1] - m0);
                sacc[j][2] = __expf(sacc[j][2] - m1);
                sacc[j][3] = __expf(sacc[j][3] - m1);
                s0 += sacc[j][0] + sacc[j][1];
                s1 += sacc[j][2] + sacc[j][3];
            }
            l0 = l0 * a0 + s0;
            l1 = l1 * a1 + s1;
#pragma unroll
            for (int jd = 0; jd < 8; jd++) {
                oacc[jd][0] *= a0; oacc[jd][1] *= a0;
                oacc[jd][2] *= a1; oacc[jd][3] *= a1;
            }

            // ---- PV over this 64-k half ----
#pragma unroll
            for (int koff = 0; koff < 2; koff++) {
                uint32_t pa[2][4];
#pragma unroll
                for (int ki = 0; ki < 2; ki++) {
                    int j0 = (koff * 2 + ki) * 2;
                    pa[ki][0] = h2(sacc[j0][0],     sacc[j0][1]);
                    pa[ki][1] = h2(sacc[j0][2],     sacc[j0][3]);
                    pa[ki][2] = h2(sacc[j0 + 1][0], sacc[j0 + 1][1]);
                    pa[ki][3] = h2(sacc[j0 + 1][2], sacc[j0 + 1][3]);
                }
#pragma unroll
                for (int jd = 0; jd < 8; jd++) {
                    uint32_t rv = vb + (uint32_t)((jd * 8 + (lane & 7)) * 272 +
                                                  ((lane >> 3) & 3) * 16 +
                                                  (khalf * 2 + koff) * 64);
                    uint32_t vF[4];
                    LDSM_X4(vF, rv);
#pragma unroll
                    for (int ki = 0; ki < 2; ki++)
                        MMAF16(oacc[jd], pa[ki], vF[ki * 2], vF[ki * 2 + 1]);
                }
            }
        }
        __syncthreads();
        st = (st + 1) % 3;
    }

    // ---- epilogue: normalize, fp16 store (proj GEMM input) ----
    l0 += __shfl_xor_sync(0xffffffffu, l0, 1);
    l0 += __shfl_xor_sync(0xffffffffu, l0, 2);
    l1 += __shfl_xor_sync(0xffffffffu, l1, 1);
    l1 += __shfl_xor_sync(0xffffffffu, l1, 2);
    const float inv0 = 1.f / l0, inv1 = 1.f / l1;
    const size_t y0 = ((size_t)(b * T_) + row_a) * C_ + h * 64;
    const size_t y1 = ((size_t)(b * T_) + row_a + 8) * C_ + h * 64;
#pragma unroll
    for (int jd = 0; jd < 8; jd++) {
        int d = jd * 8 + c2;
        *(uint32_t*)(g_yf + y0 + d) = h2(oacc[jd][0] * inv0, oacc[jd][1] * inv0);
        *(uint32_t*)(g_yf + y1 + d) = h2(oacc[jd][2] * inv1, oacc[jd][3] * inv1);
    }
}

// ---------------- launch ------------------------------------------------------------
extern "C" void kernel_launch(void* const* d_in, const int* in_sizes, int n_in,
                              void* d_out, int out_size) {
    (void)in_sizes; (void)n_in; (void)out_size;
    const float* x      = (const float*)d_in[0];
    const float* W_attn = (const float*)d_in[1];
    const float* b_attn = (const float*)d_in[2];
    const float* W_proj = (const float*)d_in[3];
    const float* b_proj = (const float*)d_in[4];
    float* out = (float*)d_out;

    cudaFuncSetAttribute(attn_mma_kernel, cudaFuncAttributeMaxDynamicSharedMemorySize,
                         ATTN_SMEM);
    cudaFuncSetAttribute(tc_gemm_kernel<N1_, 1>,
                         cudaFuncAttributeMaxDynamicSharedMemorySize, GEMM_SMEM);
    cudaFuncSetAttribute(tc_gemm_kernel<C_, 0>,
                         cudaFuncAttributeMaxDynamicSharedMemorySize, GEMM_SMEM);

    prep_kernel<<<PREP_BLOCKS, 256>>>(x, W_attn, W_proj);

    tc_gemm_kernel<N1_, 1><<<dim3(N1_ / 128, M_ / 128), 256, GEMM_SMEM>>>(b_attn, nullptr);

    attn_mma_kernel<<<(T_ / 128) * BHD, 256, ATTN_SMEM>>>();

    tc_gemm_kernel<C_, 0><<<dim3(C_ / 128, M_ / 128), 256, GEMM_SMEM>>>(b_proj, out);
}

// round 13
// speedup vs baseline: 1.0011x; 1.0011x over previous
#include <cuda_runtime.h>
#include <cuda_bf16.h>
#include <cuda_fp16.h>
#include <math.h>
#include <cstdint>

// Fixed problem shapes
#define B_   4
#define T_   2048
#define C_   768
#define H_   12
#define D_   64
#define M_   (B_ * T_)    // 8192
#define N1_  (3 * C_)     // 2304
#define BHD  (B_ * H_)    // 48

// ---------------- scratch (device globals; referenced ONLY in device code) --------
__device__ float g_cosT[T_ * (D_ / 2)];
__device__ float g_sinT[T_ * (D_ / 2)];

// fp16 operand buffers (single-pass everywhere; fp32 accumulate)
__device__ __half g_xf[M_ * C_];         // x
__device__ __half g_yf[M_ * C_];         // attn out
__device__ __half g_waf[N1_ * C_];       // W_attn^T [N][K]
__device__ __half g_wpf[C_ * C_];        // W_proj^T [N][K]
__device__ __half g_qh[BHD * T_ * D_];   // roped q (scaled 1/8), [B,H,T,D]
__device__ __half g_kh[BHD * T_ * D_];   // roped k
__device__ __half g_vth[BHD * D_ * T_];  // V^T [B,H,D,T]

// ---------------- helpers -----------------------------------------------------------
__device__ __forceinline__ uint32_t smem_u32(const void* p) {
    uint32_t a;
    asm("{ .reg .u64 t; cvta.to.shared.u64 t, %1; cvt.u32.u64 %0, t; }" : "=r"(a) : "l"(p));
    return a;
}
#define LDSM_X4(r, a)                                                           \
    asm volatile("ldmatrix.sync.aligned.m8n8.x4.shared.b16 {%0,%1,%2,%3},[%4];" \
        : "=r"((r)[0]), "=r"((r)[1]), "=r"((r)[2]), "=r"((r)[3]) : "r"(a))
#define MMAF16(d, a, b0, b1)                                                    \
    asm volatile("mma.sync.aligned.m16n8k16.row.col.f32.f16.f16.f32 "           \
        "{%0,%1,%2,%3},{%4,%5,%6,%7},{%8,%9},{%0,%1,%2,%3};"                    \
        : "+f"((d)[0]), "+f"((d)[1]), "+f"((d)[2]), "+f"((d)[3])                \
        : "r"((a)[0]), "r"((a)[1]), "r"((a)[2]), "r"((a)[3]), "r"(b0), "r"(b1))
#define CP16(dst, src) \
    asm volatile("cp.async.cg.shared.global [%0], [%1], 16;" :: "r"(dst), "l"(src))

__device__ __forceinline__ uint32_t h2(float a, float b) {
    __half2 t = __floats2half2_rn(a, b);
    return *(uint32_t*)&t;
}

// ---------------- merged prep: tables + x convert + both W transposes --------------
#define PREP_XB   (M_ * C_ / 4 / 256)        // 1536
#define PREP_WAB  ((N1_ / 32) * (C_ / 32))   // 1728
#define PREP_WPB  ((C_ / 32) * (C_ / 32))    // 576
#define PREP_TB   (T_ * 32 / 256)            // 256
#define PREP_BLOCKS (PREP_XB + PREP_WAB + PREP_WPB + PREP_TB)

__global__ void prep_kernel(const float* __restrict__ x,
                            const float* __restrict__ Wa,
                            const float* __restrict__ Wp) {
    __shared__ float tile[32][33];
    const int blk = blockIdx.x;
    const int tid = threadIdx.x;

    if (blk < PREP_XB) {
        int i = blk * 256 + tid;
        float4 v = ((const float4*)x)[i];
        ((uint2*)g_xf)[i] = make_uint2(h2(v.x, v.y), h2(v.z, v.w));
        return;
    }

    const float* W;
    __half* Th;
    int N, bi;
    if (blk < PREP_XB + PREP_WAB) {
        bi = blk - PREP_XB;  W = Wa;  Th = g_waf;  N = N1_;
    } else if (blk < PREP_XB + PREP_WAB + PREP_WPB) {
        bi = blk - PREP_XB - PREP_WAB;  W = Wp;  Th = g_wpf;  N = C_;
    } else {
        int idx = (blk - PREP_XB - PREP_WAB - PREP_WPB) * 256 + tid;
        int t = idx >> 5;
        int i = idx & 31;
        double inv = exp(-((double)i / 32.0) * log(10000.0));
        double ang = (double)t * inv;
        g_cosT[idx] = (float)cos(ang);
        g_sinT[idx] = (float)sin(ang);
        return;
    }
    const int nbt = N / 32;
    const int kb = bi / nbt, nb = bi - kb * nbt;
    const int k0 = kb * 32, n0 = nb * 32;
    const int tx = tid & 31, ty = tid >> 5;
    for (int r = ty; r < 32; r += 8)
        tile[r][tx] = W[(size_t)(k0 + r) * N + n0 + tx];
    __syncthreads();
    for (int r = ty; r < 32; r += 8)
        Th[(size_t)(n0 + r) * C_ + k0 + tx] = __float2half(tile[tx][r]);
}

// ---------------- mma.sync GEMM: fp16, BK=64 (two 32-k substeps per stage) ----------
// D[128m,128n] = A[m,K].B^T[n,K] + bias. 12 double-buffered 64-k stages.
// Row stride 144B (128B data + 16 pad): conflict-free ldmatrix (144 mod 128 = 16).
#define TILE_B    18432                  // 128 rows x 144B
#define STAGE_B   (2 * TILE_B)           // A + B tiles = 36864
#define GEMM_SMEM (2 * STAGE_B)          // 73728

template <int NT, int EPI>
__global__ __launch_bounds__(256, 2) void tc_gemm_kernel(
    const float* __restrict__ bias, float* __restrict__ Cout)
{
    extern __shared__ __align__(128) char smem[];
    const uint32_t sb0 = smem_u32(smem);
    const int tid  = threadIdx.x;
    const int lane = tid & 31;
    const int warp = tid >> 5;
    const int m_w  = (warp >> 1) * 32;
    const int n_w  = (warp & 1) * 64;
    const int m0 = blockIdx.y * 128;
    const int n0 = blockIdx.x * 128;

    const __half* Asrc = (EPI == 1) ? g_xf  : g_yf;
    const __half* Bsrc = (EPI == 1) ? g_waf : g_wpf;

    auto load_chunk = [&](int kc, int st) {
        const uint32_t sbase = sb0 + (uint32_t)st * STAGE_B;
        const int k0 = kc * 64;
#pragma unroll
        for (int it = 0; it < 8; ++it) {
            int idx  = it * 256 + tid;
            int tile = idx >> 10;              // 0:A 1:B
            int r    = (idx >> 3) & 127;
            int seg  = idx & 7;
            const __half* src = tile ? Bsrc : Asrc;
            int rowbase = (tile ? n0 : m0) + r;
            const void* g = src + (size_t)rowbase * C_ + k0 + seg * 8;
            uint32_t dst = sbase + (uint32_t)tile * TILE_B + (uint32_t)(r * 144 + seg * 16);
            CP16(dst, g);
        }
        asm volatile("cp.async.commit_group;" ::: "memory");
    };

    float acc[2][8][4];
#pragma unroll
    for (int i = 0; i < 2; i++)
#pragma unroll
        for (int j = 0; j < 8; j++)
#pragma unroll
            for (int r = 0; r < 4; r++) acc[i][j][r] = 0.f;

    load_chunk(0, 0);
    const int NCHUNK = C_ / 64;   // 12
    for (int c = 0; c < NCHUNK; ++c) {
        const int st = c & 1;
        if (c + 1 < NCHUNK) {
            load_chunk(c + 1, st ^ 1);
            asm volatile("cp.async.wait_group 1;" ::: "memory");
        } else {
            asm volatile("cp.async.wait_group 0;" ::: "memory");
        }
        __syncthreads();

        const uint32_t sA = sb0 + (uint32_t)st * STAGE_B;
        const uint32_t sB = sA + TILE_B;

#pragma unroll
        for (int subk = 0; subk < 2; ++subk) {
            uint32_t af[2][2][4];
#pragma unroll
            for (int ks = 0; ks < 2; ks++)
#pragma unroll
                for (int i = 0; i < 2; i++) {
                    uint32_t ra = (uint32_t)((m_w + i * 16 + (lane & 15)) * 144 +
                                             subk * 64 + ks * 32 + ((lane >> 4) & 1) * 16);
                    LDSM_X4(af[ks][i], sA + ra);
                }
#pragma unroll
            for (int j = 0; j < 8; j++) {
                uint32_t rb = (uint32_t)((n_w + j * 8 + (lane & 7)) * 144 +
                                         subk * 64 + ((lane >> 3) & 3) * 16);
                uint32_t bF[4];
                LDSM_X4(bF, sB + rb);
#pragma unroll
                for (int ks = 0; ks < 2; ks++)
#pragma unroll
                    for (int i = 0; i < 2; i++)
                        MMAF16(acc[i][j], af[ks][i], bF[ks * 2], bF[ks * 2 + 1]);
            }
        }
        __syncthreads();
    }

    // ---- stage results (bias added) into smem ----
    float* stg = (float*)smem;   // 128 x 132
#pragma unroll
    for (int i = 0; i < 2; i++) {
        int row = m_w + i * 16 + (lane >> 2);
#pragma unroll
        for (int j = 0; j < 8; j++) {
            int col = n_w + j * 8 + (lane & 3) * 2;
            float b0 = bias[n0 + col], b1 = bias[n0 + col + 1];
            stg[row * 132 + col]           = acc[i][j][0] + b0;
            stg[row * 132 + col + 1]       = acc[i][j][1] + b1;
            stg[(row + 8) * 132 + col]     = acc[i][j][2] + b0;
            stg[(row + 8) * 132 + col + 1] = acc[i][j][3] + b1;
        }
    }
    __syncthreads();

    if (EPI == 0) {
#pragma unroll
        for (int it = 0; it < 16; ++it) {
            int idx = it * 256 + tid;
            int ml = idx >> 5;
            int c4 = (idx & 31) * 4;
            float4 v = *(const float4*)(stg + ml * 132 + c4);
            *(float4*)(Cout + (size_t)(m0 + ml) * NT + n0 + c4) = v;
        }
    } else {
        const int which = n0 / C_;               // 0=q 1=k 2=v
        const int hbase = (n0 % C_) / 64;
        const int bb = m0 >> 11;
        const int t0 = m0 & (T_ - 1);
        if (which < 2) {
            __half* dh = which ? g_kh : g_qh;
            const float sc = which ? 1.0f : 0.125f;
#pragma unroll
            for (int it = 0; it < 16; ++it) {
                int idx = it * 256 + tid;
                int ml = idx >> 5;
                int hl = (idx >> 4) & 1;
                int d  = (idx & 15) * 2;
                int t  = t0 + ml;
                float c0 = g_cosT[(t << 5) + d],     s0 = g_sinT[(t << 5) + d];
                float c1 = g_cosT[(t << 5) + d + 1], s1 = g_sinT[(t << 5) + d + 1];
                const float* row = stg + ml * 132 + hl * 64 + d;
                float x1a = row[0],  x1b = row[1];
                float x2a = row[32], x2b = row[33];
                float y1a = (x1a * c0 + x2a * s0) * sc;
                float y1b = (x1b * c1 + x2b * s1) * sc;
                float y2a = (-x1a * s0 + x2a * c0) * sc;
                float y2b = (-x1b * s1 + x2b * c1) * sc;
                size_t o = ((size_t)(bb * H_ + hbase + hl) * T_ + t) * 64 + d;
                *(uint32_t*)(dh + o)      = h2(y1a, y1b);
                *(uint32_t*)(dh + o + 32) = h2(y2a, y2b);
            }
        } else {
#pragma unroll
            for (int it = 0; it < 32; ++it) {
                int idx  = it * 256 + tid;
                int dcol = idx >> 6;
                int tp   = (idx & 63) * 2;
                int hl = dcol >> 6;
                int dd = dcol & 63;
                float v0 = stg[tp * 132 + dcol];
                float v1 = stg[(tp + 1) * 132 + dcol];
                size_t o = ((size_t)(bb * H_ + hbase + hl) * 64 + dd) * T_ + t0 + tp;
                *(uint32_t*)(g_vth + o) = h2(v0, v1);
            }
        }
    }
}

// ---------------- Tensor-core flash attention: fp16, 2 CTA/SM, 2-stage ring --------
// (round-11 structure: 128-k stages, softmax/PV in two 64-k halves, LPT order)
#define KSTG  (128 * 144)                // 18432
#define VSTG  (64 * 272)                 // 17408
#define STG_BYTES (KSTG + VSTG)          // 35840
#define ATTN_SMEM (2 * STG_BYTES)        // 71680

__global__ __launch_bounds__(256, 2) void attn_mma_kernel() {
    extern __shared__ __align__(128) char sm[];
    const uint32_t sb = smem_u32(sm);
    const int tid  = threadIdx.x;
    const int lane = tid & 31;
    const int w    = tid >> 5;
    const int bh   = (int)blockIdx.x % BHD;
    const int qb   = (T_ / 128) - 1 - (int)blockIdx.x / BHD;
    const int b    = bh / H_;
    const int h    = bh - b * H_;
    const size_t hb = (size_t)bh * T_ * D_;
    const int qbase = qb * 128;
    const int r0 = lane >> 2;
    const int c2 = (lane & 3) * 2;
    const int row_a = qbase + w * 16 + r0;

    uint32_t qf[4][4];
#pragma unroll
    for (int ks = 0; ks < 4; ks++) {
        int d = ks * 16 + c2;
        size_t o0 = hb + (size_t)row_a * 64 + d;
        size_t o1 = hb + (size_t)(row_a + 8) * 64 + d;
        qf[ks][0] = *(const uint32_t*)(g_qh + o0);
        qf[ks][1] = *(const uint32_t*)(g_qh + o1);
        qf[ks][2] = *(const uint32_t*)(g_qh + o0 + 8);
        qf[ks][3] = *(const uint32_t*)(g_qh + o1 + 8);
    }

    const __half* kh = g_kh + hb;
    const __half* vh = g_vth + hb;

    auto load_stage = [&](int kt, int st) {
        const uint32_t sbase = sb + (uint32_t)st * STG_BYTES;
        const int kbase = kt * 128;
#pragma unroll
        for (int it = 0; it < 4; ++it) {
            int idx = it * 256 + tid;
            int r   = idx >> 3;
            int seg = idx & 7;
            const void* g = kh + (size_t)(kbase + r) * 64 + seg * 8;
            CP16(sbase + (uint32_t)(r * 144 + seg * 16), g);
        }
#pragma unroll
        for (int it = 0; it < 4; ++it) {
            int idx = it * 256 + tid;
            int r   = idx >> 4;
            int seg = idx & 15;
            const void* g = vh + (size_t)r * T_ + kbase + seg * 8;
            CP16(sbase + (uint32_t)(KSTG + r * 272 + seg * 16), g);
        }
        asm volatile("cp.async.commit_group;" ::: "memory");
    };

    float oacc[8][4];
#pragma unroll
    for (int jd = 0; jd < 8; jd++)
#pragma unroll
        for (int e = 0; e < 4; e++) oacc[jd][e] = 0.f;
    float m0 = -1e30f, m1 = -1e30f, l0 = 0.f, l1 = 0.f;

    load_stage(0, 0);

    for (int kt = 0; kt <= qb; kt++) {
        const int st = kt & 1;
        if (kt < qb) {
            load_stage(kt + 1, st ^ 1);
            asm volatile("cp.async.wait_group 1;" ::: "memory");
        } else {
            asm volatile("cp.async.wait_group 0;" ::: "memory");
        }
        __syncthreads();

        const uint32_t kb = sb + (uint32_t)st * STG_BYTES;
        const uint32_t vb = kb + KSTG;

#pragma unroll
        for (int khalf = 0; khalf < 2; khalf++) {
            if (kt == qb && khalf == 1 && w < 4) continue;

            float sacc[8][4];
#pragma unroll
            for (int j = 0; j < 8; j++)
#pragma unroll
                for (int e = 0; e < 4; e++) sacc[j][e] = 0.f;

#pragma unroll
            for (int j = 0; j < 8; j++) {
                uint32_t rbase = kb + (uint32_t)((khalf * 64 + j * 8 + (lane & 7)) * 144 +
                                                 ((lane >> 3) & 3) * 16);
#pragma unroll
                for (int dh = 0; dh < 2; dh++) {
                    uint32_t bF[4];
                    LDSM_X4(bF, rbase + dh * 64);
#pragma unroll
                    for (int ki = 0; ki < 2; ki++)
                        MMAF16(sacc[j], qf[dh * 2 + ki], bF[ki * 2], bF[ki * 2 + 1]);
                }
            }

            if (kt == qb) {
                const int kb0 = kt * 128 + khalf * 64;
#pragma unroll
                for (int j = 0; j < 8; j++) {
                    int col = kb0 + j * 8 + c2;
                    if (col > row_a)         sacc[j][0] = -1e30f;
                    if (col + 1 > row_a)     sacc[j][1] = -1e30f;
                    if (col > row_a + 8)     sacc[j][2] = -1e30f;
                    if (col + 1 > row_a + 8) sacc[j][3] = -1e30f;
                }
            }

            float mx0 = -1e30f, mx1 = -1e30f;
#pragma unroll
            for (int j = 0; j < 8; j++) {
                mx0 = fmaxf(mx0, fmaxf(sacc[j][0], sacc[j][1]));
                mx1 = fmaxf(mx1, fmaxf(sacc[j][2], sacc[j][3]));
            }
            mx0 = fmaxf(mx0, __shfl_xor_sync(0xffffffffu, mx0, 1));
            mx0 = fmaxf(mx0, __shfl_xor_sync(0xffffffffu, mx0, 2));
            mx1 = fmaxf(mx1, __shfl_xor_sync(0xffffffffu, mx1, 1));
            mx1 = fmaxf(mx1, __shfl_xor_sync(0xffffffffu, mx1, 2));
            float mn0 = fmaxf(m0, mx0), mn1 = fmaxf(m1, mx1);
            float a0 = __expf(m0 - mn0), a1 = __expf(m1 - mn1);
            m0 = mn0; m1 = mn1;
            float s0 = 0.f, s1 = 0.f;
#pragma unroll
            for (int j = 0; j < 8; j++) {
                sacc[j][0] = __expf(sacc[j][0] - m0);
                sacc[j][1] = __expf(sacc[j][1] - m0);
                sacc[j][2] = __expf(sacc[j][2] - m1);
                sacc[j][3] = __expf(sacc[j][3] - m1);
                s0 += sacc[j][0] + sacc[j][1];
                s1 += sacc[j][2] + sacc[j][3];
            }
            l0 = l0 * a0 + s0;
            l1 = l1 * a1 + s1;
#pragma unroll
            for (int jd = 0; jd < 8; jd++) {
                oacc[jd][0] *= a0; oacc[jd][1] *= a0;
                oacc[jd][2] *= a1; oacc[jd][3] *= a1;
            }

#pragma unroll
            for (int koff = 0; koff < 2; koff++) {
                uint32_t pa[2][4];
#pragma unroll
                for (int ki = 0; ki < 2; ki++) {
                    int j0 = (koff * 2 + ki) * 2;
                    pa[ki][0] = h2(sacc[j0][0],     sacc[j0][1]);
                    pa[ki][1] = h2(sacc[j0][2],     sacc[j0][3]);
                    pa[ki][2] = h2(sacc[j0 + 1][0], sacc[j0 + 1][1]);
                    pa[ki][3] = h2(sacc[j0 + 1][2], sacc[j0 + 1][3]);
                }
#pragma unroll
                for (int jd = 0; jd < 8; jd++) {
                    uint32_t rv = vb + (uint32_t)((jd * 8 + (lane & 7)) * 272 +
                                                  ((lane >> 3) & 3) * 16 +
                                                  (khalf * 2 + koff) * 64);
                    uint32_t vF[4];
                    LDSM_X4(vF, rv);
#pragma unroll
                    for (int ki = 0; ki < 2; ki++)
                        MMAF16(oacc[jd], pa[ki], vF[ki * 2], vF[ki * 2 + 1]);
                }
            }
        }
        __syncthreads();
    }

    l0 += __shfl_xor_sync(0xffffffffu, l0, 1);
    l0 += __shfl_xor_sync(0xffffffffu, l0, 2);
    l1 += __shfl_xor_sync(0xffffffffu, l1, 1);
    l1 += __shfl_xor_sync(0xffffffffu, l1, 2);
    const float inv0 = 1.f / l0, inv1 = 1.f / l1;
    const size_t y0 = ((size_t)(b * T_) + row_a) * C_ + h * 64;
    const size_t y1 = ((size_t)(b * T_) + row_a + 8) * C_ + h * 64;
#pragma unroll
    for (int jd = 0; jd < 8; jd++) {
        int d = jd * 8 + c2;
        *(uint32_t*)(g_yf + y0 + d) = h2(oacc[jd][0] * inv0, oacc[jd][1] * inv0);
        *(uint32_t*)(g_yf + y1 + d) = h2(oacc[jd][2] * inv1, oacc[jd][3] * inv1);
    }
}

// ---------------- launch ------------------------------------------------------------
extern "C" void kernel_launch(void* const* d_in, const int* in_sizes, int n_in,
                              void* d_out, int out_size) {
    (void)in_sizes; (void)n_in; (void)out_size;
    const float* x      = (const float*)d_in[0];
    const float* W_attn = (const float*)d_in[1];
    const float* b_attn = (const float*)d_in[2];
    const float* W_proj = (const float*)d_in[3];
    const float* b_proj = (const float*)d_in[4];
    float* out = (float*)d_out;

    cudaFuncSetAttribute(attn_mma_kernel, cudaFuncAttributeMaxDynamicSharedMemorySize,
                         ATTN_SMEM);
    cudaFuncSetAttribute(tc_gemm_kernel<N1_, 1>,
                         cudaFuncAttributeMaxDynamicSharedMemorySize, GEMM_SMEM);
    cudaFuncSetAttribute(tc_gemm_kernel<C_, 0>,
                         cudaFuncAttributeMaxDynamicSharedMemorySize, GEMM_SMEM);

    prep_kernel<<<PREP_BLOCKS, 256>>>(x, W_attn, W_proj);

    tc_gemm_kernel<N1_, 1><<<dim3(N1_ / 128, M_ / 128), 256, GEMM_SMEM>>>(b_attn, nullptr);

    attn_mma_kernel<<<(T_ / 128) * BHD, 256, ATTN_SMEM>>>();

    tc_gemm_kernel<C_, 0><<<dim3(C_ / 128, M_ / 128), 256, GEMM_SMEM>>>(b_proj, out);
}

// round 14
// speedup vs baseline: 1.0177x; 1.0166x over previous
#include <cuda_runtime.h>
#include <cuda_bf16.h>
#include <cuda_fp16.h>
#include <math.h>
#include <cstdint>

// Fixed problem shapes
#define B_   4
#define T_   2048
#define C_   768
#define H_   12
#define D_   64
#define M_   (B_ * T_)    // 8192
#define N1_  (3 * C_)     // 2304
#define BHD  (B_ * H_)    // 48

// ---------------- scratch (device globals; referenced ONLY in device code) --------
__device__ float g_cosT[T_ * (D_ / 2)];
__device__ float g_sinT[T_ * (D_ / 2)];

// fp16 operand buffers (single-pass everywhere; fp32 accumulate)
__device__ __half g_xf[M_ * C_];         // x
__device__ __half g_yf[M_ * C_];         // attn out
__device__ __half g_waf[N1_ * C_];       // W_attn^T [N][K]
__device__ __half g_wpf[C_ * C_];        // W_proj^T [N][K]
__device__ __half g_qh[BHD * T_ * D_];   // roped q (scaled 1/8), [B,H,T,D]
__device__ __half g_kh[BHD * T_ * D_];   // roped k
__device__ __half g_vth[BHD * D_ * T_];  // V^T [B,H,D,T]

// ---------------- helpers -----------------------------------------------------------
__device__ __forceinline__ uint32_t smem_u32(const void* p) {
    uint32_t a;
    asm("{ .reg .u64 t; cvta.to.shared.u64 t, %1; cvt.u32.u64 %0, t; }" : "=r"(a) : "l"(p));
    return a;
}
#define LDSM_X4(r, a)                                                           \
    asm volatile("ldmatrix.sync.aligned.m8n8.x4.shared.b16 {%0,%1,%2,%3},[%4];" \
        : "=r"((r)[0]), "=r"((r)[1]), "=r"((r)[2]), "=r"((r)[3]) : "r"(a))
#define MMAF16(d, a, b0, b1)                                                    \
    asm volatile("mma.sync.aligned.m16n8k16.row.col.f32.f16.f16.f32 "           \
        "{%0,%1,%2,%3},{%4,%5,%6,%7},{%8,%9},{%0,%1,%2,%3};"                    \
        : "+f"((d)[0]), "+f"((d)[1]), "+f"((d)[2]), "+f"((d)[3])                \
        : "r"((a)[0]), "r"((a)[1]), "r"((a)[2]), "r"((a)[3]), "r"(b0), "r"(b1))
#define CP16(dst, src) \
    asm volatile("cp.async.cg.shared.global [%0], [%1], 16;" :: "r"(dst), "l"(src))

__device__ __forceinline__ uint32_t h2(float a, float b) {
    __half2 t = __floats2half2_rn(a, b);
    return *(uint32_t*)&t;
}

// ---------------- merged prep: tables + x convert + both W transposes --------------
#define PREP_XB   (M_ * C_ / 4 / 256)        // 1536
#define PREP_WAB  ((N1_ / 32) * (C_ / 32))   // 1728
#define PREP_WPB  ((C_ / 32) * (C_ / 32))    // 576
#define PREP_TB   (T_ * 32 / 256)            // 256
#define PREP_BLOCKS (PREP_XB + PREP_WAB + PREP_WPB + PREP_TB)

__global__ void prep_kernel(const float* __restrict__ x,
                            const float* __restrict__ Wa,
                            const float* __restrict__ Wp) {
    __shared__ float tile[32][33];
    const int blk = blockIdx.x;
    const int tid = threadIdx.x;

    if (blk < PREP_XB) {
        int i = blk * 256 + tid;
        float4 v = ((const float4*)x)[i];
        ((uint2*)g_xf)[i] = make_uint2(h2(v.x, v.y), h2(v.z, v.w));
        return;
    }

    const float* W;
    __half* Th;
    int N, bi;
    if (blk < PREP_XB + PREP_WAB) {
        bi = blk - PREP_XB;  W = Wa;  Th = g_waf;  N = N1_;
    } else if (blk < PREP_XB + PREP_WAB + PREP_WPB) {
        bi = blk - PREP_XB - PREP_WAB;  W = Wp;  Th = g_wpf;  N = C_;
    } else {
        int idx = (blk - PREP_XB - PREP_WAB - PREP_WPB) * 256 + tid;
        int t = idx >> 5;
        int i = idx & 31;
        double inv = exp(-((double)i / 32.0) * log(10000.0));
        double ang = (double)t * inv;
        g_cosT[idx] = (float)cos(ang);
        g_sinT[idx] = (float)sin(ang);
        return;
    }
    const int nbt = N / 32;
    const int kb = bi / nbt, nb = bi - kb * nbt;
    const int k0 = kb * 32, n0 = nb * 32;
    const int tx = tid & 31, ty = tid >> 5;
    for (int r = ty; r < 32; r += 8)
        tile[r][tx] = W[(size_t)(k0 + r) * N + n0 + tx];
    __syncthreads();
    for (int r = ty; r < 32; r += 8)
        Th[(size_t)(n0 + r) * C_ + k0 + tx] = __float2half(tile[tx][r]);
}

// ---------------- mma.sync GEMM: fp16, BK=32, 4-stage ring, 1 sync/iter -------------
// D[128m,128n] = A[m,K].B^T[n,K] + bias. 24 k-chunks; cp.async ring depth 4
// (wait_group 2). Single __syncthreads per iteration (safe with >=3 stages:
// load(c+3) overwrites stage (c-1), whose readers all passed the barrier at
// the top of iteration c).
#define TILE_B    10240                  // 128 rows x 80B
#define STAGE_B   (2 * TILE_B)           // A + B = 20480
#define NSTG      4
#define GEMM_SMEM (NSTG * STAGE_B)       // 81920 (epilogue stage 67584 fits)

template <int NT, int EPI>
__global__ __launch_bounds__(256, 2) void tc_gemm_kernel(
    const float* __restrict__ bias, float* __restrict__ Cout)
{
    extern __shared__ __align__(128) char smem[];
    const uint32_t sb0 = smem_u32(smem);
    const int tid  = threadIdx.x;
    const int lane = tid & 31;
    const int warp = tid >> 5;
    const int m_w  = (warp >> 1) * 32;
    const int n_w  = (warp & 1) * 64;
    const int m0 = blockIdx.y * 128;
    const int n0 = blockIdx.x * 128;

    const __half* Asrc = (EPI == 1) ? g_xf  : g_yf;
    const __half* Bsrc = (EPI == 1) ? g_waf : g_wpf;

    auto load_chunk = [&](int kc, int st) {
        const uint32_t sbase = sb0 + (uint32_t)st * STAGE_B;
        const int k0 = kc * 32;
#pragma unroll
        for (int it = 0; it < 4; ++it) {
            int idx  = it * 256 + tid;
            int tile = idx >> 9;               // 0:A 1:B
            int r    = (idx >> 2) & 127;
            int seg  = idx & 3;
            const __half* src = tile ? Bsrc : Asrc;
            int rowbase = (tile ? n0 : m0) + r;
            const void* g = src + (size_t)rowbase * C_ + k0 + seg * 8;
            uint32_t dst = sbase + (uint32_t)tile * TILE_B + (uint32_t)(r * 80 + seg * 16);
            CP16(dst, g);
        }
        asm volatile("cp.async.commit_group;" ::: "memory");
    };

    float acc[2][8][4];
#pragma unroll
    for (int i = 0; i < 2; i++)
#pragma unroll
        for (int j = 0; j < 8; j++)
#pragma unroll
            for (int r = 0; r < 4; r++) acc[i][j][r] = 0.f;

    const int NCHUNK = C_ / 32;   // 24
    load_chunk(0, 0);
    load_chunk(1, 1);
    load_chunk(2, 2);

    for (int c = 0; c < NCHUNK; ++c) {
        const int rem = NCHUNK - 1 - c;
        if (rem >= 2)      asm volatile("cp.async.wait_group 2;" ::: "memory");
        else if (rem == 1) asm volatile("cp.async.wait_group 1;" ::: "memory");
        else               asm volatile("cp.async.wait_group 0;" ::: "memory");
        __syncthreads();

        const uint32_t sA = sb0 + (uint32_t)(c & 3) * STAGE_B;
        const uint32_t sB = sA + TILE_B;

        uint32_t af[2][2][4];
#pragma unroll
        for (int ks = 0; ks < 2; ks++)
#pragma unroll
            for (int i = 0; i < 2; i++) {
                uint32_t ra = (uint32_t)((m_w + i * 16 + (lane & 15)) * 80 +
                                         ks * 32 + ((lane >> 4) & 1) * 16);
                LDSM_X4(af[ks][i], sA + ra);
            }
#pragma unroll
        for (int j = 0; j < 8; j++) {
            uint32_t rb = (uint32_t)((n_w + j * 8 + (lane & 7)) * 80 +
                                     ((lane >> 3) & 3) * 16);
            uint32_t bF[4];
            LDSM_X4(bF, sB + rb);
#pragma unroll
            for (int ks = 0; ks < 2; ks++)
#pragma unroll
                for (int i = 0; i < 2; i++)
                    MMAF16(acc[i][j], af[ks][i], bF[ks * 2], bF[ks * 2 + 1]);
        }

        if (c + 3 < NCHUNK) load_chunk(c + 3, (c + 3) & 3);
    }
    __syncthreads();   // protect smem reuse by epilogue staging

    // ---- stage results (bias added) into smem ----
    float* stg = (float*)smem;   // 128 x 132
#pragma unroll
    for (int i = 0; i < 2; i++) {
        int row = m_w + i * 16 + (lane >> 2);
#pragma unroll
        for (int j = 0; j < 8; j++) {
            int col = n_w + j * 8 + (lane & 3) * 2;
            float b0 = bias[n0 + col], b1 = bias[n0 + col + 1];
            stg[row * 132 + col]           = acc[i][j][0] + b0;
            stg[row * 132 + col + 1]       = acc[i][j][1] + b1;
            stg[(row + 8) * 132 + col]     = acc[i][j][2] + b0;
            stg[(row + 8) * 132 + col + 1] = acc[i][j][3] + b1;
        }
    }
    __syncthreads();

    if (EPI == 0) {
#pragma unroll
        for (int it = 0; it < 16; ++it) {
            int idx = it * 256 + tid;
            int ml = idx >> 5;
            int c4 = (idx & 31) * 4;
            float4 v = *(const float4*)(stg + ml * 132 + c4);
            *(float4*)(Cout + (size_t)(m0 + ml) * NT + n0 + c4) = v;
        }
    } else {
        const int which = n0 / C_;               // 0=q 1=k 2=v
        const int hbase = (n0 % C_) / 64;
        const int bb = m0 >> 11;
        const int t0 = m0 & (T_ - 1);
        if (which < 2) {
            __half* dh = which ? g_kh : g_qh;
            const float sc = which ? 1.0f : 0.125f;
#pragma unroll
            for (int it = 0; it < 16; ++it) {
                int idx = it * 256 + tid;
                int ml = idx >> 5;
                int hl = (idx >> 4) & 1;
                int d  = (idx & 15) * 2;
                int t  = t0 + ml;
                float c0 = g_cosT[(t << 5) + d],     s0 = g_sinT[(t << 5) + d];
                float c1 = g_cosT[(t << 5) + d + 1], s1 = g_sinT[(t << 5) + d + 1];
                const float* row = stg + ml * 132 + hl * 64 + d;
                float x1a = row[0],  x1b = row[1];
                float x2a = row[32], x2b = row[33];
                float y1a = (x1a * c0 + x2a * s0) * sc;
                float y1b = (x1b * c1 + x2b * s1) * sc;
                float y2a = (-x1a * s0 + x2a * c0) * sc;
                float y2b = (-x1b * s1 + x2b * c1) * sc;
                size_t o = ((size_t)(bb * H_ + hbase + hl) * T_ + t) * 64 + d;
                *(uint32_t*)(dh + o)      = h2(y1a, y1b);
                *(uint32_t*)(dh + o + 32) = h2(y2a, y2b);
            }
        } else {
#pragma unroll
            for (int it = 0; it < 32; ++it) {
                int idx  = it * 256 + tid;
                int dcol = idx >> 6;
                int tp   = (idx & 63) * 2;
                int hl = dcol >> 6;
                int dd = dcol & 63;
                float v0 = stg[tp * 132 + dcol];
                float v1 = stg[(tp + 1) * 132 + dcol];
                size_t o = ((size_t)(bb * H_ + hbase + hl) * 64 + dd) * T_ + t0 + tp;
                *(uint32_t*)(g_vth + o) = h2(v0, v1);
            }
        }
    }
}

// ---------------- Tensor-core flash attention: fp16, 2 CTA/SM, 2-stage ring --------
#define KSTG  (128 * 144)                // 18432
#define VSTG  (64 * 272)                 // 17408
#define STG_BYTES (KSTG + VSTG)          // 35840
#define ATTN_SMEM (2 * STG_BYTES)        // 71680

__global__ __launch_bounds__(256, 2) void attn_mma_kernel() {
    extern __shared__ __align__(128) char sm[];
    const uint32_t sb = smem_u32(sm);
    const int tid  = threadIdx.x;
    const int lane = tid & 31;
    const int w    = tid >> 5;
    const int bh   = (int)blockIdx.x % BHD;
    const int qb   = (T_ / 128) - 1 - (int)blockIdx.x / BHD;
    const int b    = bh / H_;
    const int h    = bh - b * H_;
    const size_t hb = (size_t)bh * T_ * D_;
    const int qbase = qb * 128;
    const int r0 = lane >> 2;
    const int c2 = (lane & 3) * 2;
    const int row_a = qbase + w * 16 + r0;

    uint32_t qf[4][4];
#pragma unroll
    for (int ks = 0; ks < 4; ks++) {
        int d = ks * 16 + c2;
        size_t o0 = hb + (size_t)row_a * 64 + d;
        size_t o1 = hb + (size_t)(row_a + 8) * 64 + d;
        qf[ks][0] = *(const uint32_t*)(g_qh + o0);
        qf[ks][1] = *(const uint32_t*)(g_qh + o1);
        qf[ks][2] = *(const uint32_t*)(g_qh + o0 + 8);
        qf[ks][3] = *(const uint32_t*)(g_qh + o1 + 8);
    }

    const __half* kh = g_kh + hb;
    const __half* vh = g_vth + hb;

    auto load_stage = [&](int kt, int st) {
        const uint32_t sbase = sb + (uint32_t)st * STG_BYTES;
        const int kbase = kt * 128;
#pragma unroll
        for (int it = 0; it < 4; ++it) {
            int idx = it * 256 + tid;
            int r   = idx >> 3;
            int seg = idx & 7;
            const void* g = kh + (size_t)(kbase + r) * 64 + seg * 8;
            CP16(sbase + (uint32_t)(r * 144 + seg * 16), g);
        }
#pragma unroll
        for (int it = 0; it < 4; ++it) {
            int idx = it * 256 + tid;
            int r   = idx >> 4;
            int seg = idx & 15;
            const void* g = vh + (size_t)r * T_ + kbase + seg * 8;
            CP16(sbase + (uint32_t)(KSTG + r * 272 + seg * 16), g);
        }
        asm volatile("cp.async.commit_group;" ::: "memory");
    };

    float oacc[8][4];
#pragma unroll
    for (int jd = 0; jd < 8; jd++)
#pragma unroll
        for (int e = 0; e < 4; e++) oacc[jd][e] = 0.f;
    float m0 = -1e30f, m1 = -1e30f, l0 = 0.f, l1 = 0.f;

    load_stage(0, 0);

    for (int kt = 0; kt <= qb; kt++) {
        const int st = kt & 1;
        if (kt < qb) {
            load_stage(kt + 1, st ^ 1);
            asm volatile("cp.async.wait_group 1;" ::: "memory");
        } else {
            asm volatile("cp.async.wait_group 0;" ::: "memory");
        }
        __syncthreads();

        const uint32_t kb = sb + (uint32_t)st * STG_BYTES;
        const uint32_t vb = kb + KSTG;

#pragma unroll
        for (int khalf = 0; khalf < 2; khalf++) {
            if (kt == qb && khalf == 1 && w < 4) continue;

            float sacc[8][4];
#pragma unroll
            for (int j = 0; j < 8; j++)
#pragma unroll
                for (int e = 0; e < 4; e++) sacc[j][e] = 0.f;

#pragma unroll
            for (int j = 0; j < 8; j++) {
                uint32_t rbase = kb + (uint32_t)((khalf * 64 + j * 8 + (lane & 7)) * 144 +
                                                 ((lane >> 3) & 3) * 16);
#pragma unroll
                for (int dh = 0; dh < 2; dh++) {
                    uint32_t bF[4];
                    LDSM_X4(bF, rbase + dh * 64);
#pragma unroll
                    for (int ki = 0; ki < 2; ki++)
                        MMAF16(sacc[j], qf[dh * 2 + ki], bF[ki * 2], bF[ki * 2 + 1]);
                }
            }

            if (kt == qb) {
                const int kb0 = kt * 128 + khalf * 64;
#pragma unroll
                for (int j = 0; j < 8; j++) {
                    int col = kb0 + j * 8 + c2;
                    if (col > row_a)         sacc[j][0] = -1e30f;
                    if (col + 1 > row_a)     sacc[j][1] = -1e30f;
                    if (col > row_a + 8)     sacc[j][2] = -1e30f;
                    if (col + 1 > row_a + 8) sacc[j][3] = -1e30f;
                }
            }

            float mx0 = -1e30f, mx1 = -1e30f;
#pragma unroll
            for (int j = 0; j < 8; j++) {
                mx0 = fmaxf(mx0, fmaxf(sacc[j][0], sacc[j][1]));
                mx1 = fmaxf(mx1, fmaxf(sacc[j][2], sacc[j][3]));
            }
            mx0 = fmaxf(mx0, __shfl_xor_sync(0xffffffffu, mx0, 1));
            mx0 = fmaxf(mx0, __shfl_xor_sync(0xffffffffu, mx0, 2));
            mx1 = fmaxf(mx1, __shfl_xor_sync(0xffffffffu, mx1, 1));
            mx1 = fmaxf(mx1, __shfl_xor_sync(0xffffffffu, mx1, 2));
            float mn0 = fmaxf(m0, mx0), mn1 = fmaxf(m1, mx1);
            float a0 = __expf(m0 - mn0), a1 = __expf(m1 - mn1);
            m0 = mn0; m1 = mn1;
            float s0 = 0.f, s1 = 0.f;
#pragma unroll
            for (int j = 0; j < 8; j++) {
                sacc[j][0] = __expf(sacc[j][0] - m0);
                sacc[j][1] = __expf(sacc[j][1] - m0);
                sacc[j][2] = __expf(sacc[j][2] - m1);
                sacc[j][3] = __expf(sacc[j][3] - m1);
                s0 += sacc[j][0] + sacc[j][1];
                s1 += sacc[j][2] + sacc[j][3];
            }
            l0 = l0 * a0 + s0;
            l1 = l1 * a1 + s1;
#pragma unroll
            for (int jd = 0; jd < 8; jd++) {
                oacc[jd][0] *= a0; oacc[jd][1] *= a0;
                oacc[jd][2] *= a1; oacc[jd][3] *= a1;
            }

#pragma unroll
            for (int koff = 0; koff < 2; koff++) {
                uint32_t pa[2][4];
#pragma unroll
                for (int ki = 0; ki < 2; ki++) {
                    int j0 = (koff * 2 + ki) * 2;
                    pa[ki][0] = h2(sacc[j0][0],     sacc[j0][1]);
                    pa[ki][1] = h2(sacc[j0][2],     sacc[j0][3]);
                    pa[ki][2] = h2(sacc[j0 + 1][0], sacc[j0 + 1][1]);
                    pa[ki][3] = h2(sacc[j0 + 1][2], sacc[j0 + 1][3]);
                }
#pragma unroll
                for (int jd = 0; jd < 8; jd++) {
                    uint32_t rv = vb + (uint32_t)((jd * 8 + (lane & 7)) * 272 +
                                                  ((lane >> 3) & 3) * 16 +
                                                  (khalf * 2 + koff) * 64);
                    uint32_t vF[4];
                    LDSM_X4(vF, rv);
#pragma unroll
                    for (int ki = 0; ki < 2; ki++)
                        MMAF16(oacc[jd], pa[ki], vF[ki * 2], vF[ki * 2 + 1]);
                }
            }
        }
        __syncthreads();
    }

    l0 += __shfl_xor_sync(0xffffffffu, l0, 1);
    l0 += __shfl_xor_sync(0xffffffffu, l0, 2);
    l1 += __shfl_xor_sync(0xffffffffu, l1, 1);
    l1 += __shfl_xor_sync(0xffffffffu, l1, 2);
    const float inv0 = 1.f / l0, inv1 = 1.f / l1;
    const size_t y0 = ((size_t)(b * T_) + row_a) * C_ + h * 64;
    const size_t y1 = ((size_t)(b * T_) + row_a + 8) * C_ + h * 64;
#pragma unroll
    for (int jd = 0; jd < 8; jd++) {
        int d = jd * 8 + c2;
        *(uint32_t*)(g_yf + y0 + d) = h2(oacc[jd][0] * inv0, oacc[jd][1] * inv0);
        *(uint32_t*)(g_yf + y1 + d) = h2(oacc[jd][2] * inv1, oacc[jd][3] * inv1);
    }
}

// ---------------- launch ------------------------------------------------------------
extern "C" void kernel_launch(void* const* d_in, const int* in_sizes, int n_in,
                              void* d_out, int out_size) {
    (void)in_sizes; (void)n_in; (void)out_size;
    const float* x      = (const float*)d_in[0];
    const float* W_attn = (const float*)d_in[1];
    const float* b_attn = (const float*)d_in[2];
    const float* W_proj = (const float*)d_in[3];
    const float* b_proj = (const float*)d_in[4];
    float* out = (float*)d_out;

    cudaFuncSetAttribute(attn_mma_kernel, cudaFuncAttributeMaxDynamicSharedMemorySize,
                         ATTN_SMEM);
    cudaFuncSetAttribute(tc_gemm_kernel<N1_, 1>,
                         cudaFuncAttributeMaxDynamicSharedMemorySize, GEMM_SMEM);
    cudaFuncSetAttribute(tc_gemm_kernel<C_, 0>,
                         cudaFuncAttributeMaxDynamicSharedMemorySize, GEMM_SMEM);

    prep_kernel<<<PREP_BLOCKS, 256>>>(x, W_attn, W_proj);

    tc_gemm_kernel<N1_, 1><<<dim3(N1_ / 128, M_ / 128), 256, GEMM_SMEM>>>(b_attn, nullptr);

    attn_mma_kernel<<<(T_ / 128) * BHD, 256, ATTN_SMEM>>>();

    tc_gemm_kernel<C_, 0><<<dim3(C_ / 128, M_ / 128), 256, GEMM_SMEM>>>(b_proj, out);
}

// round 16
// speedup vs baseline: 1.0303x; 1.0124x over previous
#include <cuda_runtime.h>
#include <cuda_bf16.h>
#include <cuda_fp16.h>
#include <math.h>
#include <cstdint>

// Fixed problem shapes
#define B_   4
#define T_   2048
#define C_   768
#define H_   12
#define D_   64
#define M_   (B_ * T_)    // 8192
#define N1_  (3 * C_)     // 2304
#define BHD  (B_ * H_)    // 48

// ---------------- scratch (device globals; referenced ONLY in device code) --------
__device__ float g_cosT[T_ * (D_ / 2)];
__device__ float g_sinT[T_ * (D_ / 2)];

// fp16 operand buffers (single-pass everywhere; fp32 accumulate)
__device__ __half g_xf[M_ * C_];         // x
__device__ __half g_yf[M_ * C_];         // attn out
__device__ __half g_waf[N1_ * C_];       // W_attn^T [N][K]
__device__ __half g_wpf[C_ * C_];        // W_proj^T [N][K]
__device__ __half g_qh[BHD * T_ * D_];   // roped q (scaled 1/8), [B,H,T,D]
__device__ __half g_kh[BHD * T_ * D_];   // roped k
__device__ __half g_vth[BHD * D_ * T_];  // V^T [B,H,D,T]

// ---------------- helpers -----------------------------------------------------------
__device__ __forceinline__ uint32_t smem_u32(const void* p) {
    uint32_t a;
    asm("{ .reg .u64 t; cvta.to.shared.u64 t, %1; cvt.u32.u64 %0, t; }" : "=r"(a) : "l"(p));
    return a;
}
#define LDSM_X4(r, a)                                                           \
    asm volatile("ldmatrix.sync.aligned.m8n8.x4.shared.b16 {%0,%1,%2,%3},[%4];" \
        : "=r"((r)[0]), "=r"((r)[1]), "=r"((r)[2]), "=r"((r)[3]) : "r"(a))
#define MMAF16(d, a, b0, b1)                                                    \
    asm volatile("mma.sync.aligned.m16n8k16.row.col.f32.f16.f16.f32 "           \
        "{%0,%1,%2,%3},{%4,%5,%6,%7},{%8,%9},{%0,%1,%2,%3};"                    \
        : "+f"((d)[0]), "+f"((d)[1]), "+f"((d)[2]), "+f"((d)[3])                \
        : "r"((a)[0]), "r"((a)[1]), "r"((a)[2]), "r"((a)[3]), "r"(b0), "r"(b1))
#define CP16(dst, src) \
    asm volatile("cp.async.cg.shared.global [%0], [%1], 16;" :: "r"(dst), "l"(src))

__device__ __forceinline__ uint32_t h2(float a, float b) {
    __half2 t = __floats2half2_rn(a, b);
    return *(uint32_t*)&t;
}

// ---------------- merged prep: tables + x convert + both W transposes --------------
#define PREP_XB   (M_ * C_ / 4 / 256)        // 1536
#define PREP_WAB  ((N1_ / 32) * (C_ / 32))   // 1728
#define PREP_WPB  ((C_ / 32) * (C_ / 32))    // 576
#define PREP_TB   (T_ * 32 / 256)            // 256
#define PREP_BLOCKS (PREP_XB + PREP_WAB + PREP_WPB + PREP_TB)

__global__ void prep_kernel(const float* __restrict__ x,
                            const float* __restrict__ Wa,
                            const float* __restrict__ Wp) {
    __shared__ float tile[32][33];
    const int blk = blockIdx.x;
    const int tid = threadIdx.x;

    if (blk < PREP_XB) {
        int i = blk * 256 + tid;
        float4 v = ((const float4*)x)[i];
        ((uint2*)g_xf)[i] = make_uint2(h2(v.x, v.y), h2(v.z, v.w));
        return;
    }

    const float* W;
    __half* Th;
    int N, bi;
    if (blk < PREP_XB + PREP_WAB) {
        bi = blk - PREP_XB;  W = Wa;  Th = g_waf;  N = N1_;
    } else if (blk < PREP_XB + PREP_WAB + PREP_WPB) {
        bi = blk - PREP_XB - PREP_WAB;  W = Wp;  Th = g_wpf;  N = C_;
    } else {
        int idx = (blk - PREP_XB - PREP_WAB - PREP_WPB) * 256 + tid;
        int t = idx >> 5;
        int i = idx & 31;
        double inv = exp(-((double)i / 32.0) * log(10000.0));
        double ang = (double)t * inv;
        g_cosT[idx] = (float)cos(ang);
        g_sinT[idx] = (float)sin(ang);
        return;
    }
    const int nbt = N / 32;
    const int kb = bi / nbt, nb = bi - kb * nbt;
    const int k0 = kb * 32, n0 = nb * 32;
    const int tx = tid & 31, ty = tid >> 5;
    for (int r = ty; r < 32; r += 8)
        tile[r][tx] = W[(size_t)(k0 + r) * N + n0 + tx];
    __syncthreads();
    for (int r = ty; r < 32; r += 8)
        Th[(size_t)(n0 + r) * C_ + k0 + tx] = __float2half(tile[tx][r]);
}

// ---------------- mma.sync GEMM: fp16, BK=64, 3-stage ring, 1 sync/iter -------------
// CORRECT ordering: wait_group (drain own copies) -> __syncthreads (publish all
// threads' copies) -> compute stage c%3 -> issue load(c+2) into stage (c-1)%3
// (its readers all passed this iteration's barrier). Prologue = 2 loads; at
// iteration c, committed = 2+min(c,10), needed = c+1 -> wait_group 1 (0 last).
#define TILE_B    18432                  // 128 rows x 144B
#define STAGE_B   (2 * TILE_B)           // A + B = 36864
#define GEMM_SMEM (3 * STAGE_B)          // 110592 (epilogue stage 67584 fits)

template <int NT, int EPI>
__global__ __launch_bounds__(256, 2) void tc_gemm_kernel(
    const float* __restrict__ bias, float* __restrict__ Cout)
{
    extern __shared__ __align__(128) char smem[];
    const uint32_t sb0 = smem_u32(smem);
    const int tid  = threadIdx.x;
    const int lane = tid & 31;
    const int warp = tid >> 5;
    const int m_w  = (warp >> 1) * 32;
    const int n_w  = (warp & 1) * 64;
    const int m0 = blockIdx.y * 128;
    const int n0 = blockIdx.x * 128;

    const __half* Asrc = (EPI == 1) ? g_xf  : g_yf;
    const __half* Bsrc = (EPI == 1) ? g_waf : g_wpf;

    auto load_chunk = [&](int kc, int st) {
        const uint32_t sbase = sb0 + (uint32_t)st * STAGE_B;
        const int k0 = kc * 64;
#pragma unroll
        for (int it = 0; it < 8; ++it) {
            int idx  = it * 256 + tid;
            int tile = idx >> 10;              // 0:A 1:B
            int r    = (idx >> 3) & 127;
            int seg  = idx & 7;
            const __half* src = tile ? Bsrc : Asrc;
            int rowbase = (tile ? n0 : m0) + r;
            const void* g = src + (size_t)rowbase * C_ + k0 + seg * 8;
            uint32_t dst = sbase + (uint32_t)tile * TILE_B + (uint32_t)(r * 144 + seg * 16);
            CP16(dst, g);
        }
        asm volatile("cp.async.commit_group;" ::: "memory");
    };

    float acc[2][8][4];
#pragma unroll
    for (int i = 0; i < 2; i++)
#pragma unroll
        for (int j = 0; j < 8; j++)
#pragma unroll
            for (int r = 0; r < 4; r++) acc[i][j][r] = 0.f;

    const int NCHUNK = C_ / 64;   // 12
    load_chunk(0, 0);
    load_chunk(1, 1);

    for (int c = 0; c < NCHUNK; ++c) {
        if (c < NCHUNK - 1) asm volatile("cp.async.wait_group 1;" ::: "memory");
        else                asm volatile("cp.async.wait_group 0;" ::: "memory");
        __syncthreads();                       // publish all threads' copies

        const uint32_t sA = sb0 + (uint32_t)(c % 3) * STAGE_B;
        const uint32_t sB = sA + TILE_B;

#pragma unroll
        for (int subk = 0; subk < 2; ++subk) {
            uint32_t af[2][2][4];
#pragma unroll
            for (int ks = 0; ks < 2; ks++)
#pragma unroll
                for (int i = 0; i < 2; i++) {
                    uint32_t ra = (uint32_t)((m_w + i * 16 + (lane & 15)) * 144 +
                                             subk * 64 + ks * 32 + ((lane >> 4) & 1) * 16);
                    LDSM_X4(af[ks][i], sA + ra);
                }
#pragma unroll
            for (int j = 0; j < 8; j++) {
                uint32_t rb = (uint32_t)((n_w + j * 8 + (lane & 7)) * 144 +
                                         subk * 64 + ((lane >> 3) & 3) * 16);
                uint32_t bF[4];
                LDSM_X4(bF, sB + rb);
#pragma unroll
                for (int ks = 0; ks < 2; ks++)
#pragma unroll
                    for (int i = 0; i < 2; i++)
                        MMAF16(acc[i][j], af[ks][i], bF[ks * 2], bF[ks * 2 + 1]);
            }
        }

        // prefetch into stage (c-1)%3: its readers passed this iteration's barrier
        if (c + 2 < NCHUNK) load_chunk(c + 2, (c + 2) % 3);
    }
    __syncthreads();   // protect smem reuse by epilogue staging

    // ---- stage results (bias added) into smem ----
    float* stg = (float*)smem;   // 128 x 132
#pragma unroll
    for (int i = 0; i < 2; i++) {
        int row = m_w + i * 16 + (lane >> 2);
#pragma unroll
        for (int j = 0; j < 8; j++) {
            int col = n_w + j * 8 + (lane & 3) * 2;
            float b0 = bias[n0 + col], b1 = bias[n0 + col + 1];
            stg[row * 132 + col]           = acc[i][j][0] + b0;
            stg[row * 132 + col + 1]       = acc[i][j][1] + b1;
            stg[(row + 8) * 132 + col]     = acc[i][j][2] + b0;
            stg[(row + 8) * 132 + col + 1] = acc[i][j][3] + b1;
        }
    }
    __syncthreads();

    if (EPI == 0) {
#pragma unroll
        for (int it = 0; it < 16; ++it) {
            int idx = it * 256 + tid;
            int ml = idx >> 5;
            int c4 = (idx & 31) * 4;
            float4 v = *(const float4*)(stg + ml * 132 + c4);
            *(float4*)(Cout + (size_t)(m0 + ml) * NT + n0 + c4) = v;
        }
    } else {
        const int which = n0 / C_;               // 0=q 1=k 2=v
        const int hbase = (n0 % C_) / 64;
        const int bb = m0 >> 11;
        const int t0 = m0 & (T_ - 1);
        if (which < 2) {
            __half* dh = which ? g_kh : g_qh;
            const float sc = which ? 1.0f : 0.125f;
#pragma unroll
            for (int it = 0; it < 16; ++it) {
                int idx = it * 256 + tid;
                int ml = idx >> 5;
                int hl = (idx >> 4) & 1;
                int d  = (idx & 15) * 2;
                int t  = t0 + ml;
                float c0 = g_cosT[(t << 5) + d],     s0 = g_sinT[(t << 5) + d];
                float c1 = g_cosT[(t << 5) + d + 1], s1 = g_sinT[(t << 5) + d + 1];
                const float* row = stg + ml * 132 + hl * 64 + d;
                float x1a = row[0],  x1b = row[1];
                float x2a = row[32], x2b = row[33];
                float y1a = (x1a * c0 + x2a * s0) * sc;
                float y1b = (x1b * c1 + x2b * s1) * sc;
                float y2a = (-x1a * s0 + x2a * c0) * sc;
                float y2b = (-x1b * s1 + x2b * c1) * sc;
                size_t o = ((size_t)(bb * H_ + hbase + hl) * T_ + t) * 64 + d;
                *(uint32_t*)(dh + o)      = h2(y1a, y1b);
                *(uint32_t*)(dh + o + 32) = h2(y2a, y2b);
            }
        } else {
#pragma unroll
            for (int it = 0; it < 32; ++it) {
                int idx  = it * 256 + tid;
                int dcol = idx >> 6;
                int tp   = (idx & 63) * 2;
                int hl = dcol >> 6;
                int dd = dcol & 63;
                float v0 = stg[tp * 132 + dcol];
                float v1 = stg[(tp + 1) * 132 + dcol];
                size_t o = ((size_t)(bb * H_ + hbase + hl) * 64 + dd) * T_ + t0 + tp;
                *(uint32_t*)(g_vth + o) = h2(v0, v1);
            }
        }
    }
}

// ---------------- Tensor-core flash attention: fp16, 2 CTA/SM, 2-stage ring --------
#define KSTG  (128 * 144)                // 18432
#define VSTG  (64 * 272)                 // 17408
#define STG_BYTES (KSTG + VSTG)          // 35840
#define ATTN_SMEM (2 * STG_BYTES)        // 71680

__global__ __launch_bounds__(256, 2) void attn_mma_kernel() {
    extern __shared__ __align__(128) char sm[];
    const uint32_t sb = smem_u32(sm);
    const int tid  = threadIdx.x;
    const int lane = tid & 31;
    const int w    = tid >> 5;
    const int bh   = (int)blockIdx.x % BHD;
    const int qb   = (T_ / 128) - 1 - (int)blockIdx.x / BHD;
    const int b    = bh / H_;
    const int h    = bh - b * H_;
    const size_t hb = (size_t)bh * T_ * D_;
    const int qbase = qb * 128;
    const int r0 = lane >> 2;
    const int c2 = (lane & 3) * 2;
    const int row_a = qbase + w * 16 + r0;

    uint32_t qf[4][4];
#pragma unroll
    for (int ks = 0; ks < 4; ks++) {
        int d = ks * 16 + c2;
        size_t o0 = hb + (size_t)row_a * 64 + d;
        size_t o1 = hb + (size_t)(row_a + 8) * 64 + d;
        qf[ks][0] = *(const uint32_t*)(g_qh + o0);
        qf[ks][1] = *(const uint32_t*)(g_qh + o1);
        qf[ks][2] = *(const uint32_t*)(g_qh + o0 + 8);
        qf[ks][3] = *(const uint32_t*)(g_qh + o1 + 8);
    }

    const __half* kh = g_kh + hb;
    const __half* vh = g_vth + hb;

    auto load_stage = [&](int kt, int st) {
        const uint32_t sbase = sb + (uint32_t)st * STG_BYTES;
        const int kbase = kt * 128;
#pragma unroll
        for (int it = 0; it < 4; ++it) {
            int idx = it * 256 + tid;
            int r   = idx >> 3;
            int seg = idx & 7;
            const void* g = kh + (size_t)(kbase + r) * 64 + seg * 8;
            CP16(sbase + (uint32_t)(r * 144 + seg * 16), g);
        }
#pragma unroll
        for (int it = 0; it < 4; ++it) {
            int idx = it * 256 + tid;
            int r   = idx >> 4;
            int seg = idx & 15;
            const void* g = vh + (size_t)r * T_ + kbase + seg * 8;
            CP16(sbase + (uint32_t)(KSTG + r * 272 + seg * 16), g);
        }
        asm volatile("cp.async.commit_group;" ::: "memory");
    };

    float oacc[8][4];
#pragma unroll
    for (int jd = 0; jd < 8; jd++)
#pragma unroll
        for (int e = 0; e < 4; e++) oacc[jd][e] = 0.f;
    float m0 = -1e30f, m1 = -1e30f, l0 = 0.f, l1 = 0.f;

    load_stage(0, 0);

    for (int kt = 0; kt <= qb; kt++) {
        const int st = kt & 1;
        if (kt < qb) {
            load_stage(kt + 1, st ^ 1);
            asm volatile("cp.async.wait_group 1;" ::: "memory");
        } else {
            asm volatile("cp.async.wait_group 0;" ::: "memory");
        }
        __syncthreads();

        const uint32_t kb = sb + (uint32_t)st * STG_BYTES;
        const uint32_t vb = kb + KSTG;

#pragma unroll
        for (int khalf = 0; khalf < 2; khalf++) {
            if (kt == qb && khalf == 1 && w < 4) continue;

            float sacc[8][4];
#pragma unroll
            for (int j = 0; j < 8; j++)
#pragma unroll
                for (int e = 0; e < 4; e++) sacc[j][e] = 0.f;

#pragma unroll
            for (int j = 0; j < 8; j++) {
                uint32_t rbase = kb + (uint32_t)((khalf * 64 + j * 8 + (lane & 7)) * 144 +
                                                 ((lane >> 3) & 3) * 16);
#pragma unroll
                for (int dh = 0; dh < 2; dh++) {
                    uint32_t bF[4];
                    LDSM_X4(bF, rbase + dh * 64);
#pragma unroll
                    for (int ki = 0; ki < 2; ki++)
                        MMAF16(sacc[j], qf[dh * 2 + ki], bF[ki * 2], bF[ki * 2 + 1]);
                }
            }

            if (kt == qb) {
                const int kb0 = kt * 128 + khalf * 64;
#pragma unroll
                for (int j = 0; j < 8; j++) {
                    int col = kb0 + j * 8 + c2;
                    if (col > row_a)         sacc[j][0] = -1e30f;
                    if (col + 1 > row_a)     sacc[j][1] = -1e30f;
                    if (col > row_a + 8)     sacc[j][2] = -1e30f;
                    if (col + 1 > row_a + 8) sacc[j][3] = -1e30f;
                }
            }

            float mx0 = -1e30f, mx1 = -1e30f;
#pragma unroll
            for (int j = 0; j < 8; j++) {
                mx0 = fmaxf(mx0, fmaxf(sacc[j][0], sacc[j][1]));
                mx1 = fmaxf(mx1, fmaxf(sacc[j][2], sacc[j][3]));
            }
            mx0 = fmaxf(mx0, __shfl_xor_sync(0xffffffffu, mx0, 1));
            mx0 = fmaxf(mx0, __shfl_xor_sync(0xffffffffu, mx0, 2));
            mx1 = fmaxf(mx1, __shfl_xor_sync(0xffffffffu, mx1, 1));
            mx1 = fmaxf(mx1, __shfl_xor_sync(0xffffffffu, mx1, 2));
            float mn0 = fmaxf(m0, mx0), mn1 = fmaxf(m1, mx1);
            float a0 = __expf(m0 - mn0), a1 = __expf(m1 - mn1);
            m0 = mn0; m1 = mn1;
            float s0 = 0.f, s1 = 0.f;
#pragma unroll
            for (int j = 0; j < 8; j++) {
                sacc[j][0] = __expf(sacc[j][0] - m0);
                sacc[j][1] = __expf(sacc[j][1] - m0);
                sacc[j][2] = __expf(sacc[j][2] - m1);
                sacc[j][3] = __expf(sacc[j][3] - m1);
                s0 += sacc[j][0] + sacc[j][1];
                s1 += sacc[j][2] + sacc[j][3];
            }
            l0 = l0 * a0 + s0;
            l1 = l1 * a1 + s1;
#pragma unroll
            for (int jd = 0; jd < 8; jd++) {
                oacc[jd][0] *= a0; oacc[jd][1] *= a0;
                oacc[jd][2] *= a1; oacc[jd][3] *= a1;
            }

#pragma unroll
            for (int koff = 0; koff < 2; koff++) {
                uint32_t pa[2][4];
#pragma unroll
                for (int ki = 0; ki < 2; ki++) {
                    int j0 = (koff * 2 + ki) * 2;
                    pa[ki][0] = h2(sacc[j0][0],     sacc[j0][1]);
                    pa[ki][1] = h2(sacc[j0][2],     sacc[j0][3]);
                    pa[ki][2] = h2(sacc[j0 + 1][0], sacc[j0 + 1][1]);
                    pa[ki][3] = h2(sacc[j0 + 1][2], sacc[j0 + 1][3]);
                }
#pragma unroll
                for (int jd = 0; jd < 8; jd++) {
                    uint32_t rv = vb + (uint32_t)((jd * 8 + (lane & 7)) * 272 +
                                                  ((lane >> 3) & 3) * 16 +
                                                  (khalf * 2 + koff) * 64);
                    uint32_t vF[4];
                    LDSM_X4(vF, rv);
#pragma unroll
                    for (int ki = 0; ki < 2; ki++)
                        MMAF16(oacc[jd], pa[ki], vF[ki * 2], vF[ki * 2 + 1]);
                }
            }
        }
        __syncthreads();
    }

    l0 += __shfl_xor_sync(0xffffffffu, l0, 1);
    l0 += __shfl_xor_sync(0xffffffffu, l0, 2);
    l1 += __shfl_xor_sync(0xffffffffu, l1, 1);
    l1 += __shfl_xor_sync(0xffffffffu, l1, 2);
    const float inv0 = 1.f / l0, inv1 = 1.f / l1;
    const size_t y0 = ((size_t)(b * T_) + row_a) * C_ + h * 64;
    const size_t y1 = ((size_t)(b * T_) + row_a + 8) * C_ + h * 64;
#pragma unroll
    for (int jd = 0; jd < 8; jd++) {
        int d = jd * 8 + c2;
        *(uint32_t*)(g_yf + y0 + d) = h2(oacc[jd][0] * inv0, oacc[jd][1] * inv0);
        *(uint32_t*)(g_yf + y1 + d) = h2(oacc[jd][2] * inv1, oacc[jd][3] * inv1);
    }
}

// ---------------- launch ------------------------------------------------------------
extern "C" void kernel_launch(void* const* d_in, const int* in_sizes, int n_in,
                              void* d_out, int out_size) {
    (void)in_sizes; (void)n_in; (void)out_size;
    const float* x      = (const float*)d_in[0];
    const float* W_attn = (const float*)d_in[1];
    const float* b_attn = (const float*)d_in[2];
    const float* W_proj = (const float*)d_in[3];
    const float* b_proj = (const float*)d_in[4];
    float* out = (float*)d_out;

    cudaFuncSetAttribute(attn_mma_kernel, cudaFuncAttributeMaxDynamicSharedMemorySize,
                         ATTN_SMEM);
    cudaFuncSetAttribute(tc_gemm_kernel<N1_, 1>,
                         cudaFuncAttributeMaxDynamicSharedMemorySize, GEMM_SMEM);
    cudaFuncSetAttribute(tc_gemm_kernel<C_, 0>,
                         cudaFuncAttributeMaxDynamicSharedMemorySize, GEMM_SMEM);

    prep_kernel<<<PREP_BLOCKS, 256>>>(x, W_attn, W_proj);

    tc_gemm_kernel<N1_, 1><<<dim3(N1_ / 128, M_ / 128), 256, GEMM_SMEM>>>(b_attn, nullptr);

    attn_mma_kernel<<<(T_ / 128) * BHD, 256, ATTN_SMEM>>>();

    tc_gemm_kernel<C_, 0><<<dim3(C_ / 128, M_ / 128), 256, GEMM_SMEM>>>(b_proj, out);
}

// round 17
// speedup vs baseline: 1.0561x; 1.0250x over previous
#include <cuda_runtime.h>
#include <cuda_bf16.h>
#include <cuda_fp16.h>
#include <math.h>
#include <cstdint>

// Fixed problem shapes
#define B_   4
#define T_   2048
#define C_   768
#define H_   12
#define D_   64
#define M_   (B_ * T_)    // 8192
#define N1_  (3 * C_)     // 2304
#define BHD  (B_ * H_)    // 48

// ---------------- scratch (device globals; referenced ONLY in device code) --------
__device__ float g_cosT[T_ * (D_ / 2)];
__device__ float g_sinT[T_ * (D_ / 2)];

// fp16 operand buffers (single-pass everywhere; fp32 accumulate)
__device__ __half g_xf[M_ * C_];         // x
__device__ __half g_yf[M_ * C_];         // attn out
__device__ __half g_waf[N1_ * C_];       // W_attn^T [N][K]
__device__ __half g_wpf[C_ * C_];        // W_proj^T [N][K]
__device__ __half g_qh[BHD * T_ * D_];   // roped q (scaled 1/8), [B,H,T,D]
__device__ __half g_kh[BHD * T_ * D_];   // roped k
__device__ __half g_vth[BHD * D_ * T_];  // V^T [B,H,D,T]

// ---------------- helpers -----------------------------------------------------------
__device__ __forceinline__ uint32_t smem_u32(const void* p) {
    uint32_t a;
    asm("{ .reg .u64 t; cvta.to.shared.u64 t, %1; cvt.u32.u64 %0, t; }" : "=r"(a) : "l"(p));
    return a;
}
#define LDSM_X4(r, a)                                                           \
    asm volatile("ldmatrix.sync.aligned.m8n8.x4.shared.b16 {%0,%1,%2,%3},[%4];" \
        : "=r"((r)[0]), "=r"((r)[1]), "=r"((r)[2]), "=r"((r)[3]) : "r"(a))
#define MMAF16(d, a, b0, b1)                                                    \
    asm volatile("mma.sync.aligned.m16n8k16.row.col.f32.f16.f16.f32 "           \
        "{%0,%1,%2,%3},{%4,%5,%6,%7},{%8,%9},{%0,%1,%2,%3};"                    \
        : "+f"((d)[0]), "+f"((d)[1]), "+f"((d)[2]), "+f"((d)[3])                \
        : "r"((a)[0]), "r"((a)[1]), "r"((a)[2]), "r"((a)[3]), "r"(b0), "r"(b1))
#define CP16(dst, src) \
    asm volatile("cp.async.cg.shared.global [%0], [%1], 16;" :: "r"(dst), "l"(src))

__device__ __forceinline__ uint32_t h2(float a, float b) {
    __half2 t = __floats2half2_rn(a, b);
    return *(uint32_t*)&t;
}

// ---------------- merged prep: tables + x convert + both W transposes --------------
#define PREP_XB   (M_ * C_ / 4 / 256)        // 1536
#define PREP_WAB  ((N1_ / 32) * (C_ / 32))   // 1728
#define PREP_WPB  ((C_ / 32) * (C_ / 32))    // 576
#define PREP_TB   (T_ * 32 / 256)            // 256
#define PREP_BLOCKS (PREP_XB + PREP_WAB + PREP_WPB + PREP_TB)

__global__ void prep_kernel(const float* __restrict__ x,
                            const float* __restrict__ Wa,
                            const float* __restrict__ Wp) {
    __shared__ float tile[32][33];
    const int blk = blockIdx.x;
    const int tid = threadIdx.x;

    if (blk < PREP_XB) {
        int i = blk * 256 + tid;
        float4 v = ((const float4*)x)[i];
        ((uint2*)g_xf)[i] = make_uint2(h2(v.x, v.y), h2(v.z, v.w));
        return;
    }

    const float* W;
    __half* Th;
    int N, bi;
    if (blk < PREP_XB + PREP_WAB) {
        bi = blk - PREP_XB;  W = Wa;  Th = g_waf;  N = N1_;
    } else if (blk < PREP_XB + PREP_WAB + PREP_WPB) {
        bi = blk - PREP_XB - PREP_WAB;  W = Wp;  Th = g_wpf;  N = C_;
    } else {
        int idx = (blk - PREP_XB - PREP_WAB - PREP_WPB) * 256 + tid;
        int t = idx >> 5;
        int i = idx & 31;
        double inv = exp(-((double)i / 32.0) * log(10000.0));
        double ang = (double)t * inv;
        g_cosT[idx] = (float)cos(ang);
        g_sinT[idx] = (float)sin(ang);
        return;
    }
    const int nbt = N / 32;
    const int kb = bi / nbt, nb = bi - kb * nbt;
    const int k0 = kb * 32, n0 = nb * 32;
    const int tx = tid & 31, ty = tid >> 5;
    for (int r = ty; r < 32; r += 8)
        tile[r][tx] = W[(size_t)(k0 + r) * N + n0 + tx];
    __syncthreads();
    for (int r = ty; r < 32; r += 8)
        Th[(size_t)(n0 + r) * C_ + k0 + tx] = __float2half(tile[tx][r]);
}

// ---------------- mma.sync GEMM: fp16, BK=64, 3-stage ring, j-pipelined ldsm --------
// wait_group -> __syncthreads -> compute (B frags double-buffered one j ahead)
// -> issue load(c+2). 12 iterations, 1 barrier each.
#define TILE_B    18432                  // 128 rows x 144B
#define STAGE_B   (2 * TILE_B)           // A + B = 36864
#define GEMM_SMEM (3 * STAGE_B)          // 110592 (epilogue stage 67584 fits)

template <int NT, int EPI>
__global__ __launch_bounds__(256, 2) void tc_gemm_kernel(
    const float* __restrict__ bias, float* __restrict__ Cout)
{
    extern __shared__ __align__(128) char smem[];
    const uint32_t sb0 = smem_u32(smem);
    const int tid  = threadIdx.x;
    const int lane = tid & 31;
    const int warp = tid >> 5;
    const int m_w  = (warp >> 1) * 32;
    const int n_w  = (warp & 1) * 64;
    const int m0 = blockIdx.y * 128;
    const int n0 = blockIdx.x * 128;

    const __half* Asrc = (EPI == 1) ? g_xf  : g_yf;
    const __half* Bsrc = (EPI == 1) ? g_waf : g_wpf;

    auto load_chunk = [&](int kc, int st) {
        const uint32_t sbase = sb0 + (uint32_t)st * STAGE_B;
        const int k0 = kc * 64;
#pragma unroll
        for (int it = 0; it < 8; ++it) {
            int idx  = it * 256 + tid;
            int tile = idx >> 10;              // 0:A 1:B
            int r    = (idx >> 3) & 127;
            int seg  = idx & 7;
            const __half* src = tile ? Bsrc : Asrc;
            int rowbase = (tile ? n0 : m0) + r;
            const void* g = src + (size_t)rowbase * C_ + k0 + seg * 8;
            uint32_t dst = sbase + (uint32_t)tile * TILE_B + (uint32_t)(r * 144 + seg * 16);
            CP16(dst, g);
        }
        asm volatile("cp.async.commit_group;" ::: "memory");
    };

    float acc[2][8][4];
#pragma unroll
    for (int i = 0; i < 2; i++)
#pragma unroll
        for (int j = 0; j < 8; j++)
#pragma unroll
            for (int r = 0; r < 4; r++) acc[i][j][r] = 0.f;

    const int NCHUNK = C_ / 64;   // 12
    load_chunk(0, 0);
    load_chunk(1, 1);

    for (int c = 0; c < NCHUNK; ++c) {
        if (c < NCHUNK - 1) asm volatile("cp.async.wait_group 1;" ::: "memory");
        else                asm volatile("cp.async.wait_group 0;" ::: "memory");
        __syncthreads();                       // publish all threads' copies

        const uint32_t sA = sb0 + (uint32_t)(c % 3) * STAGE_B;
        const uint32_t sB = sA + TILE_B;
        const uint32_t rbB = (uint32_t)((n_w + (lane & 7)) * 144 + ((lane >> 3) & 3) * 16);

#pragma unroll
        for (int subk = 0; subk < 2; ++subk) {
            uint32_t af[2][2][4];
#pragma unroll
            for (int ks = 0; ks < 2; ks++)
#pragma unroll
                for (int i = 0; i < 2; i++) {
                    uint32_t ra = (uint32_t)((m_w + i * 16 + (lane & 15)) * 144 +
                                             subk * 64 + ks * 32 + ((lane >> 4) & 1) * 16);
                    LDSM_X4(af[ks][i], sA + ra);
                }

            // B fragments double-buffered one j-step ahead
            uint32_t bF[2][4];
            LDSM_X4(bF[0], sB + rbB + subk * 64);
#pragma unroll
            for (int j = 0; j < 8; j++) {
                if (j < 7)
                    LDSM_X4(bF[(j + 1) & 1], sB + rbB + (uint32_t)((j + 1) * 8 * 144) + subk * 64);
                const uint32_t* b = bF[j & 1];
#pragma unroll
                for (int ks = 0; ks < 2; ks++)
#pragma unroll
                    for (int i = 0; i < 2; i++)
                        MMAF16(acc[i][j], af[ks][i], b[ks * 2], b[ks * 2 + 1]);
            }
        }

        if (c + 2 < NCHUNK) load_chunk(c + 2, (c + 2) % 3);
    }
    __syncthreads();   // protect smem reuse by epilogue staging

    // ---- stage results (bias added) into smem ----
    float* stg = (float*)smem;   // 128 x 132
#pragma unroll
    for (int i = 0; i < 2; i++) {
        int row = m_w + i * 16 + (lane >> 2);
#pragma unroll
        for (int j = 0; j < 8; j++) {
            int col = n_w + j * 8 + (lane & 3) * 2;
            float b0 = bias[n0 + col], b1 = bias[n0 + col + 1];
            stg[row * 132 + col]           = acc[i][j][0] + b0;
            stg[row * 132 + col + 1]       = acc[i][j][1] + b1;
            stg[(row + 8) * 132 + col]     = acc[i][j][2] + b0;
            stg[(row + 8) * 132 + col + 1] = acc[i][j][3] + b1;
        }
    }
    __syncthreads();

    if (EPI == 0) {
#pragma unroll
        for (int it = 0; it < 16; ++it) {
            int idx = it * 256 + tid;
            int ml = idx >> 5;
            int c4 = (idx & 31) * 4;
            float4 v = *(const float4*)(stg + ml * 132 + c4);
            *(float4*)(Cout + (size_t)(m0 + ml) * NT + n0 + c4) = v;
        }
    } else {
        const int which = n0 / C_;               // 0=q 1=k 2=v
        const int hbase = (n0 % C_) / 64;
        const int bb = m0 >> 11;
        const int t0 = m0 & (T_ - 1);
        if (which < 2) {
            __half* dh = which ? g_kh : g_qh;
            const float sc = which ? 1.0f : 0.125f;
#pragma unroll
            for (int it = 0; it < 16; ++it) {
                int idx = it * 256 + tid;
                int ml = idx >> 5;
                int hl = (idx >> 4) & 1;
                int d  = (idx & 15) * 2;
                int t  = t0 + ml;
                float c0 = g_cosT[(t << 5) + d],     s0 = g_sinT[(t << 5) + d];
                float c1 = g_cosT[(t << 5) + d + 1], s1 = g_sinT[(t << 5) + d + 1];
                const float* row = stg + ml * 132 + hl * 64 + d;
                float x1a = row[0],  x1b = row[1];
                float x2a = row[32], x2b = row[33];
                float y1a = (x1a * c0 + x2a * s0) * sc;
                float y1b = (x1b * c1 + x2b * s1) * sc;
                float y2a = (-x1a * s0 + x2a * c0) * sc;
                float y2b = (-x1b * s1 + x2b * c1) * sc;
                size_t o = ((size_t)(bb * H_ + hbase + hl) * T_ + t) * 64 + d;
                *(uint32_t*)(dh + o)      = h2(y1a, y1b);
                *(uint32_t*)(dh + o + 32) = h2(y2a, y2b);
            }
        } else {
#pragma unroll
            for (int it = 0; it < 32; ++it) {
                int idx  = it * 256 + tid;
                int dcol = idx >> 6;
                int tp   = (idx & 63) * 2;
                int hl = dcol >> 6;
                int dd = dcol & 63;
                float v0 = stg[tp * 132 + dcol];
                float v1 = stg[(tp + 1) * 132 + dcol];
                size_t o = ((size_t)(bb * H_ + hbase + hl) * 64 + dd) * T_ + t0 + tp;
                *(uint32_t*)(g_vth + o) = h2(v0, v1);
            }
        }
    }
}

// ---------------- Tensor-core flash attention: fp16, 2 CTA/SM, 2-stage ring --------
#define KSTG  (128 * 144)                // 18432
#define VSTG  (64 * 272)                 // 17408
#define STG_BYTES (KSTG + VSTG)          // 35840
#define ATTN_SMEM (2 * STG_BYTES)        // 71680

__global__ __launch_bounds__(256, 2) void attn_mma_kernel() {
    extern __shared__ __align__(128) char sm[];
    const uint32_t sb = smem_u32(sm);
    const int tid  = threadIdx.x;
    const int lane = tid & 31;
    const int w    = tid >> 5;
    const int bh   = (int)blockIdx.x % BHD;
    const int qb   = (T_ / 128) - 1 - (int)blockIdx.x / BHD;
    const int b    = bh / H_;
    const int h    = bh - b * H_;
    const size_t hb = (size_t)bh * T_ * D_;
    const int qbase = qb * 128;
    const int r0 = lane >> 2;
    const int c2 = (lane & 3) * 2;
    const int row_a = qbase + w * 16 + r0;

    uint32_t qf[4][4];
#pragma unroll
    for (int ks = 0; ks < 4; ks++) {
        int d = ks * 16 + c2;
        size_t o0 = hb + (size_t)row_a * 64 + d;
        size_t o1 = hb + (size_t)(row_a + 8) * 64 + d;
        qf[ks][0] = *(const uint32_t*)(g_qh + o0);
        qf[ks][1] = *(const uint32_t*)(g_qh + o1);
        qf[ks][2] = *(const uint32_t*)(g_qh + o0 + 8);
        qf[ks][3] = *(const uint32_t*)(g_qh + o1 + 8);
    }

    const __half* kh = g_kh + hb;
    const __half* vh = g_vth + hb;

    auto load_stage = [&](int kt, int st) {
        const uint32_t sbase = sb + (uint32_t)st * STG_BYTES;
        const int kbase = kt * 128;
#pragma unroll
        for (int it = 0; it < 4; ++it) {
            int idx = it * 256 + tid;
            int r   = idx >> 3;
            int seg = idx & 7;
            const void* g = kh + (size_t)(kbase + r) * 64 + seg * 8;
            CP16(sbase + (uint32_t)(r * 144 + seg * 16), g);
        }
#pragma unroll
        for (int it = 0; it < 4; ++it) {
            int idx = it * 256 + tid;
            int r   = idx >> 4;
            int seg = idx & 15;
            const void* g = vh + (size_t)r * T_ + kbase + seg * 8;
            CP16(sbase + (uint32_t)(KSTG + r * 272 + seg * 16), g);
        }
        asm volatile("cp.async.commit_group;" ::: "memory");
    };

    float oacc[8][4];
#pragma unroll
    for (int jd = 0; jd < 8; jd++)
#pragma unroll
        for (int e = 0; e < 4; e++) oacc[jd][e] = 0.f;
    float m0 = -1e30f, m1 = -1e30f, l0 = 0.f, l1 = 0.f;

    load_stage(0, 0);

    for (int kt = 0; kt <= qb; kt++) {
        const int st = kt & 1;
        if (kt < qb) {
            load_stage(kt + 1, st ^ 1);
            asm volatile("cp.async.wait_group 1;" ::: "memory");
        } else {
            asm volatile("cp.async.wait_group 0;" ::: "memory");
        }
        __syncthreads();

        const uint32_t kb = sb + (uint32_t)st * STG_BYTES;
        const uint32_t vb = kb + KSTG;

#pragma unroll
        for (int khalf = 0; khalf < 2; khalf++) {
            if (kt == qb && khalf == 1 && w < 4) continue;

            float sacc[8][4];
#pragma unroll
            for (int j = 0; j < 8; j++)
#pragma unroll
                for (int e = 0; e < 4; e++) sacc[j][e] = 0.f;

#pragma unroll
            for (int j = 0; j < 8; j++) {
                uint32_t rbase = kb + (uint32_t)((khalf * 64 + j * 8 + (lane & 7)) * 144 +
                                                 ((lane >> 3) & 3) * 16);
#pragma unroll
                for (int dh = 0; dh < 2; dh++) {
                    uint32_t bF[4];
                    LDSM_X4(bF, rbase + dh * 64);
#pragma unroll
                    for (int ki = 0; ki < 2; ki++)
                        MMAF16(sacc[j], qf[dh * 2 + ki], bF[ki * 2], bF[ki * 2 + 1]);
                }
            }

            if (kt == qb) {
                const int kb0 = kt * 128 + khalf * 64;
#pragma unroll
                for (int j = 0; j < 8; j++) {
                    int col = kb0 + j * 8 + c2;
                    if (col > row_a)         sacc[j][0] = -1e30f;
                    if (col + 1 > row_a)     sacc[j][1] = -1e30f;
                    if (col > row_a + 8)     sacc[j][2] = -1e30f;
                    if (col + 1 > row_a + 8) sacc[j][3] = -1e30f;
                }
            }

            float mx0 = -1e30f, mx1 = -1e30f;
#pragma unroll
            for (int j = 0; j < 8; j++) {
                mx0 = fmaxf(mx0, fmaxf(sacc[j][0], sacc[j][1]));
                mx1 = fmaxf(mx1, fmaxf(sacc[j][2], sacc[j][3]));
            }
            mx0 = fmaxf(mx0, __shfl_xor_sync(0xffffffffu, mx0, 1));
            mx0 = fmaxf(mx0, __shfl_xor_sync(0xffffffffu, mx0, 2));
            mx1 = fmaxf(mx1, __shfl_xor_sync(0xffffffffu, mx1, 1));
            mx1 = fmaxf(mx1, __shfl_xor_sync(0xffffffffu, mx1, 2));
            float mn0 = fmaxf(m0, mx0), mn1 = fmaxf(m1, mx1);
            float a0 = __expf(m0 - mn0), a1 = __expf(m1 - mn1);
            m0 = mn0; m1 = mn1;
            float s0 = 0.f, s1 = 0.f;
#pragma unroll
            for (int j = 0; j < 8; j++) {
                sacc[j][0] = __expf(sacc[j][0] - m0);
                sacc[j][1] = __expf(sacc[j][1] - m0);
                sacc[j][2] = __expf(sacc[j][2] - m1);
                sacc[j][3] = __expf(sacc[j][3] - m1);
                s0 += sacc[j][0] + sacc[j][1];
                s1 += sacc[j][2] + sacc[j][3];
            }
            l0 = l0 * a0 + s0;
            l1 = l1 * a1 + s1;
#pragma unroll
            for (int jd = 0; jd < 8; jd++) {
                oacc[jd][0] *= a0; oacc[jd][1] *= a0;
                oacc[jd][2] *= a1; oacc[jd][3] *= a1;
            }

#pragma unroll
            for (int koff = 0; koff < 2; koff++) {
                uint32_t pa[2][4];
#pragma unroll
                for (int ki = 0; ki < 2; ki++) {
                    int j0 = (koff * 2 + ki) * 2;
                    pa[ki][0] = h2(sacc[j0][0],     sacc[j0][1]);
                    pa[ki][1] = h2(sacc[j0][2],     sacc[j0][3]);
                    pa[ki][2] = h2(sacc[j0 + 1][0], sacc[j0 + 1][1]);
                    pa[ki][3] = h2(sacc[j0 + 1][2], sacc[j0 + 1][3]);
                }
#pragma unroll
                for (int jd = 0; jd < 8; jd++) {
                    uint32_t rv = vb + (uint32_t)((jd * 8 + (lane & 7)) * 272 +
                                                  ((lane >> 3) & 3) * 16 +
                                                  (khalf * 2 + koff) * 64);
                    uint32_t vF[4];
                    LDSM_X4(vF, rv);
#pragma unroll
                    for (int ki = 0; ki < 2; ki++)
                        MMAF16(oacc[jd], pa[ki], vF[ki * 2], vF[ki * 2 + 1]);
                }
            }
        }
        __syncthreads();
    }

    l0 += __shfl_xor_sync(0xffffffffu, l0, 1);
    l0 += __shfl_xor_sync(0xffffffffu, l0, 2);
    l1 += __shfl_xor_sync(0xffffffffu, l1, 1);
    l1 += __shfl_xor_sync(0xffffffffu, l1, 2);
    const float inv0 = 1.f / l0, inv1 = 1.f / l1;
    const size_t y0 = ((size_t)(b * T_) + row_a) * C_ + h * 64;
    const size_t y1 = ((size_t)(b * T_) + row_a + 8) * C_ + h * 64;
#pragma unroll
    for (int jd = 0; jd < 8; jd++) {
        int d = jd * 8 + c2;
        *(uint32_t*)(g_yf + y0 + d) = h2(oacc[jd][0] * inv0, oacc[jd][1] * inv0);
        *(uint32_t*)(g_yf + y1 + d) = h2(oacc[jd][2] * inv1, oacc[jd][3] * inv1);
    }
}

// ---------------- launch ------------------------------------------------------------
extern "C" void kernel_launch(void* const* d_in, const int* in_sizes, int n_in,
                              void* d_out, int out_size) {
    (void)in_sizes; (void)n_in; (void)out_size;
    const float* x      = (const float*)d_in[0];
    const float* W_attn = (const float*)d_in[1];
    const float* b_attn = (const float*)d_in[2];
    const float* W_proj = (const float*)d_in[3];
    const float* b_proj = (const float*)d_in[4];
    float* out = (float*)d_out;

    cudaFuncSetAttribute(attn_mma_kernel, cudaFuncAttributeMaxDynamicSharedMemorySize,
                         ATTN_SMEM);
    cudaFuncSetAttribute(tc_gemm_kernel<N1_, 1>,
                         cudaFuncAttributeMaxDynamicSharedMemorySize, GEMM_SMEM);
    cudaFuncSetAttribute(tc_gemm_kernel<C_, 0>,
                         cudaFuncAttributeMaxDynamicSharedMemorySize, GEMM_SMEM);

    prep_kernel<<<PREP_BLOCKS, 256>>>(x, W_attn, W_proj);

    tc_gemm_kernel<N1_, 1><<<dim3(N1_ / 128, M_ / 128), 256, GEMM_SMEM>>>(b_attn, nullptr);

    attn_mma_kernel<<<(T_ / 128) * BHD, 256, ATTN_SMEM>>>();

    tc_gemm_kernel<C_, 0><<<dim3(C_ / 128, M_ / 128), 256, GEMM_SMEM>>>(b_proj, out);
}